// round 14
// baseline (speedup 1.0000x reference)
#include <cuda_runtime.h>
#include <cuda_bf16.h>
#include <cstdint>
#include <cstddef>

// ---------------- problem constants ----------------
#define B_   2
#define L_   2048
#define DM   2048          // d_model
#define DI   4096          // d_inner
#define EI   8192          // 2*d_inner
#define DS   16            // d_state
#define DTR  128           // dt_rank
#define XD   160           // dt_rank + 2*d_state
#define ML   (B_*L_)       // 4096 rows

#define KS_BC 8            // split-K for B/C sgemm
#define KS_DT 4            // split-K for dt_lo mma

// ---------------- scratch (device globals; no allocation allowed) ----------------
__device__ float g_xz  [(size_t)ML * EI];
__device__ float g_xc  [(size_t)ML * DI];   // conv+silu (exact fp32)
__device__ float g_xcr [(size_t)ML * DI];   // conv+silu (tf32-rounded)
__device__ float g_bc  [(size_t)ML * 32];   // B(16)+C(16) per row, fp32
__device__ float g_bcp [(size_t)KS_BC * ML * 32];
__device__ float g_dt  [(size_t)ML * DI];
__device__ float g_dtwc[(size_t)DI * DTR];  // tf32-rounded dt_proj_weight
__device__ float g_xpwc[(size_t)DTR * DI];  // tf32-rounded x_proj_weight rows 0..127
__device__ float g_dtlo[(size_t)ML * DTR];  // tf32 dt_lo (compact)
__device__ float g_dtlp[(size_t)KS_DT * ML * DTR];
// bf16 hi/lo split planes for the big GEMMs
__device__ __nv_bfloat16 g_hs_h [(size_t)ML * DM];
__device__ __nv_bfloat16 g_hs_l [(size_t)ML * DM];
__device__ __nv_bfloat16 g_win_h[(size_t)EI * DM];
__device__ __nv_bfloat16 g_win_l[(size_t)EI * DM];
__device__ __nv_bfloat16 g_ow_h [(size_t)DM * DI];
__device__ __nv_bfloat16 g_ow_l [(size_t)DM * DI];
__device__ __nv_bfloat16 g_y_h  [(size_t)ML * DI];
__device__ __nv_bfloat16 g_y_l  [(size_t)ML * DI];

__device__ __forceinline__ unsigned f2tf32(float f) {
    unsigned u;
    asm("cvt.rna.tf32.f32 %0, %1;" : "=r"(u) : "f"(f));
    return u;
}
__device__ __forceinline__ float tf32r(float f) {
    return __uint_as_float(f2tf32(f));
}
__device__ __forceinline__ void bf16split(float v, __nv_bfloat16& h, __nv_bfloat16& l) {
    h = __float2bfloat16(v);
    l = __float2bfloat16(v - __bfloat162float(h));
}

// ---------------- fused prep: bf16-split hs/w_in/outw + tf32-round dtw/xpw ----------------
__global__ __launch_bounds__(256)
void prep_kernel(const float* hs,   __nv_bfloat16* hsh, __nv_bfloat16* hsl, size_t n0,
                 const float* win,  __nv_bfloat16* wh,  __nv_bfloat16* wl,  size_t n1,
                 const float* ow,   __nv_bfloat16* oh,  __nv_bfloat16* ol,  size_t n2,
                 const float* dtw,  float* dtwc, size_t n3,
                 const float* xpw,  float* xpwc, size_t n4)
{
    size_t i = (size_t)blockIdx.x * blockDim.x + threadIdx.x;
    const float* s; __nv_bfloat16 *ph = nullptr, *pl = nullptr; float* pf = nullptr;
    if (i < n0) { s = hs; ph = hsh; pl = hsl; }
    else if ((i -= n0) < n1) { s = win; ph = wh; pl = wl; }
    else if ((i -= n1) < n2) { s = ow;  ph = oh; pl = ol; }
    else if ((i -= n2) < n3) { s = dtw; pf = dtwc; }
    else if ((i -= n3) < n4) { s = xpw; pf = xpwc; }
    else return;
    float4 v = ((const float4*)s)[i];
    if (pf) {
        v.x = tf32r(v.x); v.y = tf32r(v.y); v.z = tf32r(v.z); v.w = tf32r(v.w);
        ((float4*)pf)[i] = v;
    } else {
        __nv_bfloat16 h[4], l[4];
        bf16split(v.x, h[0], l[0]); bf16split(v.y, h[1], l[1]);
        bf16split(v.z, h[2], l[2]); bf16split(v.w, h[3], l[3]);
        *(uint2*)&ph[i*4] = *(uint2*)h;
        *(uint2*)&pl[i*4] = *(uint2*)l;
    }
}

// ---------------- split-K reduce: bc (8 partials) + dtlo (4 partials, tf32r) ----------------
__global__ __launch_bounds__(256)
void reduce_splitk_kernel(const float* __restrict__ bcp, float* __restrict__ bc,
                          const float* __restrict__ dtlp, float* __restrict__ dtlo)
{
    const size_t nBC = (size_t)ML * 32 / 4;
    const size_t nDT = (size_t)ML * DTR / 4;
    size_t i = (size_t)blockIdx.x * blockDim.x + threadIdx.x;
    if (i < nBC) {
        float4 a = ((const float4*)bcp)[i];
        #pragma unroll
        for (int s = 1; s < KS_BC; s++) {
            float4 p = ((const float4*)(bcp + (size_t)s * ML * 32))[i];
            a.x += p.x; a.y += p.y; a.z += p.z; a.w += p.w;
        }
        ((float4*)bc)[i] = a;
    } else if ((i -= nBC) < nDT) {
        float4 a = ((const float4*)dtlp)[i];
        #pragma unroll
        for (int s = 1; s < KS_DT; s++) {
            float4 p = ((const float4*)(dtlp + (size_t)s * ML * DTR))[i];
            a.x += p.x; a.y += p.y; a.z += p.z; a.w += p.w;
        }
        a.x = tf32r(a.x); a.y = tf32r(a.y); a.z = tf32r(a.z); a.w = tf32r(a.w);
        ((float4*)dtlo)[i] = a;
    }
}

// ---------------- async-copy + ldmatrix helpers ----------------
__device__ __forceinline__ void cp16(void* smem_dst, const void* gmem_src) {
    unsigned s = (unsigned)__cvta_generic_to_shared(smem_dst);
    asm volatile("cp.async.cg.shared.global [%0], [%1], 16;\n" :: "r"(s), "l"(gmem_src));
}
__device__ __forceinline__ void cp_commit() {
    asm volatile("cp.async.commit_group;\n");
}
__device__ __forceinline__ void cp_wait1() {
    asm volatile("cp.async.wait_group 1;\n");
}
__device__ __forceinline__ void cp_wait2() {
    asm volatile("cp.async.wait_group 2;\n");
}
__device__ __forceinline__ void ldsm4(unsigned& r0, unsigned& r1, unsigned& r2, unsigned& r3,
                                      unsigned addr) {
    asm volatile("ldmatrix.sync.aligned.m8n8.x4.shared.b16 {%0,%1,%2,%3}, [%4];"
                 : "=r"(r0), "=r"(r1), "=r"(r2), "=r"(r3) : "r"(addr));
}
#define MMA_BF16(acc, a, b) \
    asm volatile( \
        "mma.sync.aligned.m16n8k16.row.col.f32.bf16.bf16.f32 " \
        "{%0,%1,%2,%3}, {%4,%5,%6,%7}, {%8,%9}, {%0,%1,%2,%3};" \
        : "+f"(acc[0]), "+f"(acc[1]), "+f"(acc[2]), "+f"(acc[3]) \
        : "r"(a[0]), "r"(a[1]), "r"(a[2]), "r"(a[3]), "r"(b[0]), "r"(b[1]))

// =========================================================================
// BF16x3 GEMM: C = A*B^T with A,B given as bf16 hi/lo planes (a=hi+lo).
// acc += Ah*Bh + Ah*Bl + Al*Bh  (fp32 accumulate, err ~2^-16).
// BM=128, BN=256, BK=32, 512 thr (16 warps 2m x 8n), warp 64x32, 4-stage.
// Smem row = 32 hi bf16 (64B) | 32 lo bf16 (64B) = 128B, 8-chunk swizzle.
// =========================================================================
#define BSTG_A 16384u       // bytes per A stage (128 rows * 128B)
#define BSTG_B 32768u       // bytes per B stage (256 rows * 128B)

__global__ __launch_bounds__(512, 1)
void mma_gemm_bf3(int M, int N, int K,
                  const __nv_bfloat16* __restrict__ Ah,
                  const __nv_bfloat16* __restrict__ Al, int lda,
                  const __nv_bfloat16* __restrict__ Bh,
                  const __nv_bfloat16* __restrict__ Bl, int ldb,
                  float* __restrict__ C, int ldc)
{
    extern __shared__ char smem[];
    char* As = smem;                    // 4 stages * 16KB
    char* Bs = smem + 4*BSTG_A;         // 4 stages * 32KB

    const int tid  = threadIdx.x;
    const int lane = tid & 31;
    const int warp = tid >> 5;
    const int wm   = (warp & 1) * 64;
    const int wn   = (warp >> 1) * 32;
    const int bm   = blockIdx.y * 128;
    const int bn   = blockIdx.x * 256;

    // ---- loader: thread t -> row r0=t>>3 (+64 groups), chunk q=t&7 ----
    const int q   = tid & 7;
    const int r0  = tid >> 3;
    const int pq  = q ^ (r0 & 7);
    const int dB  = r0*128 + pq*16;     // byte offset within stage

    const __nv_bfloat16* gA = (q < 4 ? Ah : Al) + (size_t)(bm + r0) * lda + (q & 3) * 8;
    const __nv_bfloat16* gB = (q < 4 ? Bh : Bl) + (size_t)(bn + r0) * ldb + (q & 3) * 8;

    // ---- ldmatrix lane addressing ----
    const int g    = lane >> 3;
    const int kg   = g >> 1;            // k-half within k16
    const int sub8 = (g & 1) << 3;
    const int lr   = lane & 7;
    const unsigned aSh = (unsigned)__cvta_generic_to_shared(As);
    const unsigned bSh = (unsigned)__cvta_generic_to_shared(Bs);
    const unsigned aBase  = aSh + (unsigned)(wm + sub8 + lr) * 128;
    const unsigned bBase0 = bSh + (unsigned)(wn + sub8 + lr) * 128;
    const unsigned bBase1 = bBase0 + 16*128;
    unsigned tkh[2], tkl[2];
    #pragma unroll
    for (int ks = 0; ks < 2; ks++) {
        tkh[ks] = (unsigned)(((((ks << 1) + kg)     ^ lr) & 7) << 4);
        tkl[ks] = (unsigned)(((((ks << 1) + kg + 4) ^ lr) & 7) << 4);
    }

    const int u  = lane >> 2;
    const int li = lane & 3;

    float acc[4][4][4];
    #pragma unroll
    for (int i = 0; i < 4; i++)
        #pragma unroll
        for (int j = 0; j < 4; j++)
            #pragma unroll
            for (int r = 0; r < 4; r++) acc[i][j][r] = 0.0f;

    const int KT = K / 32;

    // ---- prologue: stages 0,1 ----
    #pragma unroll
    for (int s = 0; s < 2; s++) {
        const size_t ko = (size_t)s * 32;
        #pragma unroll
        for (int i = 0; i < 2; i++)
            cp16(As + s*BSTG_A + dB + i*8192, gA + (size_t)i*64*lda + ko);
        #pragma unroll
        for (int i = 0; i < 4; i++)
            cp16(Bs + s*BSTG_B + dB + i*8192, gB + (size_t)i*64*ldb + ko);
        cp_commit();
    }

    for (int kt = 0; kt < KT; kt++) {
        const int cur = kt & 3;
        if (kt + 2 < KT) {
            const int st = (kt + 2) & 3;
            const size_t ko = (size_t)(kt + 2) * 32;
            #pragma unroll
            for (int i = 0; i < 2; i++)
                cp16(As + st*BSTG_A + dB + i*8192, gA + (size_t)i*64*lda + ko);
            #pragma unroll
            for (int i = 0; i < 4; i++)
                cp16(Bs + st*BSTG_B + dB + i*8192, gB + (size_t)i*64*ldb + ko);
        }
        cp_commit();
        cp_wait2();
        __syncthreads();

        const unsigned aOff  = aBase  + (unsigned)cur * BSTG_A;
        const unsigned bOff0 = bBase0 + (unsigned)cur * BSTG_B;
        const unsigned bOff1 = bBase1 + (unsigned)cur * BSTG_B;

        #pragma unroll
        for (int ks = 0; ks < 2; ks++) {
            unsigned ah[4][4], bh[4][2], bl[4][2];
            #pragma unroll
            for (int i = 0; i < 4; i++)
                ldsm4(ah[i][0], ah[i][1], ah[i][2], ah[i][3],
                      aOff + (unsigned)i*2048 + tkh[ks]);
            ldsm4(bh[0][0], bh[1][0], bh[0][1], bh[1][1], bOff0 + tkh[ks]);
            ldsm4(bh[2][0], bh[3][0], bh[2][1], bh[3][1], bOff1 + tkh[ks]);
            ldsm4(bl[0][0], bl[1][0], bl[0][1], bl[1][1], bOff0 + tkl[ks]);
            ldsm4(bl[2][0], bl[3][0], bl[2][1], bl[3][1], bOff1 + tkl[ks]);

            // hi*hi and hi*lo
            #pragma unroll
            for (int i = 0; i < 4; i++)
                #pragma unroll
                for (int j = 0; j < 4; j++) {
                    MMA_BF16(acc[i][j], ah[i], bh[j]);
                    MMA_BF16(acc[i][j], ah[i], bl[j]);
                }
            // lo*hi (reload A as lo plane)
            #pragma unroll
            for (int i = 0; i < 4; i++)
                ldsm4(ah[i][0], ah[i][1], ah[i][2], ah[i][3],
                      aOff + (unsigned)i*2048 + tkl[ks]);
            #pragma unroll
            for (int i = 0; i < 4; i++)
                #pragma unroll
                for (int j = 0; j < 4; j++)
                    MMA_BF16(acc[i][j], ah[i], bh[j]);
        }
    }

    #pragma unroll
    for (int i = 0; i < 4; i++) {
        const int r0e = bm + wm + i*16 + u;
        #pragma unroll
        for (int j = 0; j < 4; j++) {
            const int c0 = bn + wn + j*8 + li*2;
            *(float2*)&C[(size_t)r0e * ldc + c0]     = make_float2(acc[i][j][0], acc[i][j][1]);
            *(float2*)&C[(size_t)(r0e+8) * ldc + c0] = make_float2(acc[i][j][2], acc[i][j][3]);
        }
    }
}

// ================= mma.sync TF32 GEMM BN=128 (pre-rounded inputs; dt path) ==========
#define TSZ32 4096
#define STB   16384u

template<int EPI, int SPLITK>
__global__ __launch_bounds__(256, 2)
void mma_gemm(int M, int N, int K,
              const float* __restrict__ A, int lda,
              const float* __restrict__ Bw, int ldb,
              float* __restrict__ C, int ldc,
              const float* __restrict__ bias)
{
    extern __shared__ float smemf[];
    float* As = smemf;
    float* Bs = smemf + 3*TSZ32;

    const int tid  = threadIdx.x;
    const int lane = tid & 31;
    const int warp = tid >> 5;
    const int wm   = (warp & 1) * 64;
    const int wn   = (warp >> 1) * 32;
    const int bm   = blockIdx.y * 128;
    int bn = 0;
    if (SPLITK) {
        const int sk = blockIdx.x;
        A  += (size_t)sk * K;
        Bw += (size_t)sk * K;
        C  += (size_t)sk * M * ldc;
    } else {
        bn = blockIdx.x * 128;
    }

    const int q     = tid & 7;
    const int r0    = tid >> 3;
    const int pq    = q ^ (r0 & 7);
    const int dBase = r0*32 + pq*4;

    const float* gA = A  + (size_t)(bm + r0) * lda + q*4;
    const float* gB = Bw + (size_t)(bn + r0) * ldb + q*4;

    const int g    = lane >> 3;
    const int kg   = g >> 1;
    const int sub8 = (g & 1) << 3;
    const int lr   = lane & 7;
    const unsigned aSh = (unsigned)__cvta_generic_to_shared(As);
    const unsigned bSh = (unsigned)__cvta_generic_to_shared(Bs);
    const unsigned aBase  = aSh + (unsigned)(wm + sub8 + lr) * 128;
    const unsigned bBase0 = bSh + (unsigned)(wn + sub8 + lr) * 128;
    const unsigned bBase1 = bBase0 + 16*128;
    unsigned tks[4];
    #pragma unroll
    for (int ks = 0; ks < 4; ks++)
        tks[ks] = (unsigned)(((((ks << 1) + kg) ^ lr) & 7) << 4);

    const int u  = lane >> 2;
    const int li = lane & 3;

    float acc[4][4][4];
    #pragma unroll
    for (int i = 0; i < 4; i++)
        #pragma unroll
        for (int j = 0; j < 4; j++)
            #pragma unroll
            for (int r = 0; r < 4; r++) acc[i][j][r] = 0.0f;

    const int KT = K / 32;

    #pragma unroll
    for (int s = 0; s < 2; s++) {
        const size_t ko = (size_t)s * 32;
        #pragma unroll
        for (int i = 0; i < 4; i++) {
            cp16(As + s*TSZ32 + dBase + i*1024, gA + (size_t)i*32*lda + ko);
            cp16(Bs + s*TSZ32 + dBase + i*1024, gB + (size_t)i*32*ldb + ko);
        }
        cp_commit();
    }
    cp_wait1();
    __syncthreads();

    for (int kt = 0; kt < KT; kt++) {
        const int cur = kt % 3;
        if (kt + 2 < KT) {
            const int st = (kt + 2) % 3;
            const size_t ko = (size_t)(kt + 2) * 32;
            #pragma unroll
            for (int i = 0; i < 4; i++) {
                cp16(As + st*TSZ32 + dBase + i*1024, gA + (size_t)i*32*lda + ko);
                cp16(Bs + st*TSZ32 + dBase + i*1024, gB + (size_t)i*32*ldb + ko);
            }
        }
        cp_commit();

        const unsigned aOff  = aBase  + (unsigned)cur * STB;
        const unsigned bOff0 = bBase0 + (unsigned)cur * STB;
        const unsigned bOff1 = bBase1 + (unsigned)cur * STB;

        #pragma unroll
        for (int ks = 0; ks < 4; ks++) {
            unsigned af[4][4];
            unsigned bf[4][2];
            #pragma unroll
            for (int i = 0; i < 4; i++)
                ldsm4(af[i][0], af[i][1], af[i][2], af[i][3],
                      aOff + (unsigned)i*2048 + tks[ks]);
            ldsm4(bf[0][0], bf[1][0], bf[0][1], bf[1][1], bOff0 + tks[ks]);
            ldsm4(bf[2][0], bf[3][0], bf[2][1], bf[3][1], bOff1 + tks[ks]);

            #pragma unroll
            for (int i = 0; i < 4; i++)
                #pragma unroll
                for (int j = 0; j < 4; j++) {
                    asm volatile(
                        "mma.sync.aligned.m16n8k8.row.col.f32.tf32.tf32.f32 "
                        "{%0,%1,%2,%3}, {%4,%5,%6,%7}, {%8,%9}, {%0,%1,%2,%3};"
                        : "+f"(acc[i][j][0]), "+f"(acc[i][j][1]),
                          "+f"(acc[i][j][2]), "+f"(acc[i][j][3])
                        : "r"(af[i][0]), "r"(af[i][1]), "r"(af[i][2]), "r"(af[i][3]),
                          "r"(bf[j][0]), "r"(bf[j][1]));
                }
        }

        cp_wait1();
        __syncthreads();
    }

    #pragma unroll
    for (int i = 0; i < 4; i++) {
        const int r0e = bm + wm + i*16 + u;
        #pragma unroll
        for (int j = 0; j < 4; j++) {
            const int c0 = bn + wn + j*8 + li*2;
            float v0 = acc[i][j][0], v1 = acc[i][j][1];
            float v2 = acc[i][j][2], v3 = acc[i][j][3];
            if (EPI == 1) {
                const float bA = bias[c0], bB = bias[c0+1];
                v0 += bA; v1 += bB; v2 += bA; v3 += bB;
                v0 = (v0 > 20.0f) ? v0 : log1pf(__expf(v0));
                v1 = (v1 > 20.0f) ? v1 : log1pf(__expf(v1));
                v2 = (v2 > 20.0f) ? v2 : log1pf(__expf(v2));
                v3 = (v3 > 20.0f) ? v3 : log1pf(__expf(v3));
            }
            *(float2*)&C[(size_t)r0e * ldc + c0]     = make_float2(v0, v1);
            *(float2*)&C[(size_t)(r0e+8) * ldc + c0] = make_float2(v2, v3);
        }
    }
}

// ---------------- fp32 tiled SGEMM, split-K (B/C part of x_proj: N=32) ----------------
template<int BM, int BN, int BK, int TM, int TN>
__global__ __launch_bounds__(256)
void sgemm_splitk_kernel(int M, int N, int KC,
                         const float* __restrict__ A, int lda,
                         const float* __restrict__ Bw, int ldb,
                         float* __restrict__ C, int ldc)
{
    __shared__ float As[BK][BM];
    __shared__ float Bs[BK][BN];

    const int tid = threadIdx.x;
    const int tx  = tid & 15;
    const int ty  = tid >> 4;
    const int bm  = blockIdx.y * BM;
    const int sk  = blockIdx.x;
    const size_t k0base = (size_t)sk * KC;
    C += (size_t)sk * M * ldc;

    float acc[TM][TN];
    #pragma unroll
    for (int i = 0; i < TM; i++)
        #pragma unroll
        for (int j = 0; j < TN; j++) acc[i][j] = 0.0f;

    const int a_m = tid / (BK/4);
    const int a_k = (tid % (BK/4)) * 4;

    for (int k0 = 0; k0 < KC; k0 += BK) {
        if (tid < (BM*BK/4)) {
            float4 v = *(const float4*)&A[(size_t)(bm + a_m)*lda + k0base + k0 + a_k];
            As[a_k+0][a_m] = v.x; As[a_k+1][a_m] = v.y;
            As[a_k+2][a_m] = v.z; As[a_k+3][a_m] = v.w;
        }
        if (tid < (BN*BK/4)) {
            float4 v = *(const float4*)&Bw[(size_t)a_m*ldb + k0base + k0 + a_k];
            Bs[a_k+0][a_m] = v.x; Bs[a_k+1][a_m] = v.y;
            Bs[a_k+2][a_m] = v.z; Bs[a_k+3][a_m] = v.w;
        }
        __syncthreads();

        #pragma unroll
        for (int k = 0; k < BK; k++) {
            float rm[TM], rn[TN];
            #pragma unroll
            for (int i = 0; i < TM; i++) rm[i] = As[k][ty*TM + i];
            #pragma unroll
            for (int j = 0; j < TN; j++) rn[j] = Bs[k][tx*TN + j];
            #pragma unroll
            for (int i = 0; i < TM; i++)
                #pragma unroll
                for (int j = 0; j < TN; j++)
                    acc[i][j] += rm[i] * rn[j];
        }
        __syncthreads();
    }

    #pragma unroll
    for (int i = 0; i < TM; i++) {
        const int m = bm + ty*TM + i;
        #pragma unroll
        for (int j = 0; j < TN; j++) {
            const int n = tx*TN + j;
            C[(size_t)m*ldc + n] = acc[i][j];
        }
    }
}

// ---------------- depthwise causal conv(k=4) + bias + silu, L-chunked ----------------
#define CLC 128
__global__ __launch_bounds__(256)
void conv_silu_kernel(const float* __restrict__ xz,
                      const float* __restrict__ w,
                      const float* __restrict__ bias,
                      float* __restrict__ xc,
                      float* __restrict__ xcr)
{
    const int d  = blockIdx.x * blockDim.x + threadIdx.x;
    const int b  = blockIdx.z;
    const int l0 = blockIdx.y * CLC;

    const float w0 = w[d*4+0], w1 = w[d*4+1], w2 = w[d*4+2], w3 = w[d*4+3];
    const float bi = bias[d];
    const float* px = xz  + ((size_t)b * L_ + l0) * EI + d;
    float*       po = xc  + ((size_t)b * L_ + l0) * DI + d;
    float*       pr = xcr + ((size_t)b * L_ + l0) * DI + d;

    float x0 = 0.f, x1 = 0.f, x2 = 0.f;
    if (l0 > 0) {
        x0 = px[-(size_t)3 * EI];
        x1 = px[-(size_t)2 * EI];
        x2 = px[-(size_t)1 * EI];
    }
    #pragma unroll 4
    for (int l = 0; l < CLC; l++) {
        float x3 = px[(size_t)l * EI];
        float v  = w0*x0 + w1*x1 + w2*x2 + w3*x3 + bi;
        v = v / (1.0f + __expf(-v));
        po[(size_t)l * DI] = v;
        pr[(size_t)l * DI] = tf32r(v);
        x0 = x1; x1 = x2; x2 = x3;
    }
}

// ---------------- selective scan: state-parallel + cp.async smem staging ----------------
// Output y emitted as bf16 hi/lo planes (exact split; out_proj is bf16x3).
#define SCH 16
__global__ __launch_bounds__(128)
void scan_kernel(const float* __restrict__ xz,
                 const float* __restrict__ xc,
                 const float* __restrict__ dt,
                 const float* __restrict__ bc,
                 const float* __restrict__ A_log,
                 const float* __restrict__ Dp,
                 __nv_bfloat16* __restrict__ yh,
                 __nv_bfloat16* __restrict__ yl)
{
    __shared__ float s_dt[2][SCH][32];
    __shared__ float s_xc[2][SCH][32];
    __shared__ float s_z [2][SCH][32];
    __shared__ float s_bc[2][SCH][32];

    const int b    = blockIdx.y;
    const int tid  = threadIdx.x;
    const int wid  = tid >> 5;
    const int lane = tid & 31;
    const int sub  = lane & 3;
    const int cidx = wid * 8 + (lane >> 2);
    const int d0   = blockIdx.x * 32;
    const int d    = d0 + cidx;

    const int lrow = tid >> 3;
    const int lcol = (tid & 7) * 4;

    float negA[4];
    #pragma unroll
    for (int j = 0; j < 4; j++)
        negA[j] = -__expf(A_log[d*DS + sub*4 + j]);
    const float negA0 = -__expf(A_log[d*DS]);

    bool chain = (negA0 != 0.0f);
    #pragma unroll
    for (int n = 1; n < DS; n++) {
        float na = -__expf(A_log[d*DS + n]);
        float r  = na - (float)(n+1) * negA0;
        if (fabsf(r) > 1e-4f * fabsf(na)) chain = false;
    }

    const float Dd = Dp[d];
    float h[4] = {0.f, 0.f, 0.f, 0.f};

    const size_t rb = (size_t)b * L_;
    const float* pdt = dt + rb * DI;
    const float* pxc = xc + rb * DI;
    const float* pz  = xz + rb * EI + DI;
    const float* pbc = bc + rb * 32;
    __nv_bfloat16* pyh = yh + rb * DI + d;
    __nv_bfloat16* pyl = yl + rb * DI + d;

    #pragma unroll
    for (int c = 0; c < 2; c++) {
        const size_t l0 = (size_t)c * SCH;
        cp16(&s_dt[c][lrow][lcol], pdt + (l0 + lrow) * DI + d0 + lcol);
        cp16(&s_xc[c][lrow][lcol], pxc + (l0 + lrow) * DI + d0 + lcol);
        cp16(&s_z [c][lrow][lcol], pz  + (l0 + lrow) * EI + d0 + lcol);
        cp16(&s_bc[c][lrow][lcol], pbc + (l0 + lrow) * 32 + lcol);
        cp_commit();
    }
    cp_wait1();
    __syncthreads();

    const int NCH = L_ / SCH;
    for (int c = 0; c < NCH; c++) {
        const int buf = c & 1;

        #pragma unroll 4
        for (int i = 0; i < SCH; i++) {
            const float dtv = s_dt[buf][i][cidx];
            const float xv  = s_xc[buf][i][cidx];
            const float zv  = s_z [buf][i][cidx];
            const float bc0 = s_bc[buf][i][lane];

            float dA[4];
            if (chain) {
                const float b1 = __expf(dtv * negA0);
                const float b2 = b1*b1, b3 = b2*b1, b4 = b2*b2;
                const float b8 = b4*b4, b12 = b8*b4;
                const float pw = (sub == 0) ? 1.0f : (sub == 1) ? b4 : (sub == 2) ? b8 : b12;
                dA[0] = pw*b1; dA[1] = pw*b2; dA[2] = pw*b3; dA[3] = pw*b4;
            } else {
                #pragma unroll
                for (int j = 0; j < 4; j++) dA[j] = __expf(dtv * negA[j]);
            }

            const float du = dtv * xv;
            float yp = 0.0f;
            #pragma unroll
            for (int j = 0; j < 4; j++) {
                const float Bn = __shfl_sync(0xFFFFFFFFu, bc0, sub*4 + j);
                const float Cn = __shfl_sync(0xFFFFFFFFu, bc0, 16 + sub*4 + j);
                h[j] = h[j] * dA[j] + du * Bn;
                yp  += h[j] * Cn;
            }
            yp += __shfl_xor_sync(0xFFFFFFFFu, yp, 1);
            yp += __shfl_xor_sync(0xFFFFFFFFu, yp, 2);

            if (sub == 0) {
                const float yv = yp + xv * Dd;
                const float zs = zv / (1.0f + __expf(-zv));
                __nv_bfloat16 hb, lb;
                bf16split(yv * zs, hb, lb);
                pyh[(size_t)(c*SCH + i) * DI] = hb;
                pyl[(size_t)(c*SCH + i) * DI] = lb;
            }
        }

        __syncthreads();
        if (c + 2 < NCH) {
            const size_t l0 = (size_t)(c + 2) * SCH;
            cp16(&s_dt[buf][lrow][lcol], pdt + (l0 + lrow) * DI + d0 + lcol);
            cp16(&s_xc[buf][lrow][lcol], pxc + (l0 + lrow) * DI + d0 + lcol);
            cp16(&s_z [buf][lrow][lcol], pz  + (l0 + lrow) * EI + d0 + lcol);
            cp16(&s_bc[buf][lrow][lcol], pbc + (l0 + lrow) * 32 + lcol);
        }
        cp_commit();
        cp_wait1();
        __syncthreads();
    }
}

// ---------------- launch ----------------
extern "C" void kernel_launch(void* const* d_in, const int* in_sizes, int n_in,
                              void* d_out, int out_size)
{
    const float* hs    = (const float*)d_in[0];
    const float* w_in  = (const float*)d_in[1];
    const float* convw = (const float*)d_in[2];
    const float* convb = (const float*)d_in[3];
    const float* xpw   = (const float*)d_in[4];
    const float* dtw   = (const float*)d_in[5];
    const float* dtb   = (const float*)d_in[6];
    const float* outw  = (const float*)d_in[7];
    const float* Alog  = (const float*)d_in[8];
    const float* Dp    = (const float*)d_in[9];
    float*       out   = (float*)d_out;

    float *xz, *xc, *xcr, *bc, *bcp, *dtb_, *dtwc, *xpwc, *dtlo, *dtlp;
    __nv_bfloat16 *hsh, *hsl, *wih, *wil, *owh, *owl, *yh, *yl;
    cudaGetSymbolAddress((void**)&xz,   g_xz);
    cudaGetSymbolAddress((void**)&xc,   g_xc);
    cudaGetSymbolAddress((void**)&xcr,  g_xcr);
    cudaGetSymbolAddress((void**)&bc,   g_bc);
    cudaGetSymbolAddress((void**)&bcp,  g_bcp);
    cudaGetSymbolAddress((void**)&dtb_, g_dt);
    cudaGetSymbolAddress((void**)&dtwc, g_dtwc);
    cudaGetSymbolAddress((void**)&xpwc, g_xpwc);
    cudaGetSymbolAddress((void**)&dtlo, g_dtlo);
    cudaGetSymbolAddress((void**)&dtlp, g_dtlp);
    cudaGetSymbolAddress((void**)&hsh,  g_hs_h);
    cudaGetSymbolAddress((void**)&hsl,  g_hs_l);
    cudaGetSymbolAddress((void**)&wih,  g_win_h);
    cudaGetSymbolAddress((void**)&wil,  g_win_l);
    cudaGetSymbolAddress((void**)&owh,  g_ow_h);
    cudaGetSymbolAddress((void**)&owl,  g_ow_l);
    cudaGetSymbolAddress((void**)&yh,   g_y_h);
    cudaGetSymbolAddress((void**)&yl,   g_y_l);

    const dim3 t256(256);
    const size_t msmem = 6 * TSZ32 * sizeof(float);            // 98304 (tf32 mma)
    const size_t bsmem = 4 * (BSTG_A + BSTG_B);                // 196608 (bf16x3)

    cudaFuncSetAttribute((const void*)&mma_gemm<1,0>, cudaFuncAttributeMaxDynamicSharedMemorySize, (int)msmem);
    cudaFuncSetAttribute((const void*)&mma_gemm<0,1>, cudaFuncAttributeMaxDynamicSharedMemorySize, (int)msmem);
    cudaFuncSetAttribute((const void*)&mma_gemm_bf3,  cudaFuncAttributeMaxDynamicSharedMemorySize, (int)bsmem);

    // 0) fused prep: bf16-split hs/w_in/outw; tf32-round dtw/xpw
    {
        const size_t n0 = (size_t)ML*DM/4, n1 = (size_t)EI*DM/4,
                     n2 = (size_t)DM*DI/4, n3 = (size_t)DI*DTR/4,
                     n4 = (size_t)DTR*DI/4;
        const size_t nt = n0 + n1 + n2 + n3 + n4;
        prep_kernel<<<(unsigned)((nt+255)/256), t256>>>(
            hs, hsh, hsl, n0, w_in, wih, wil, n1, outw, owh, owl, n2,
            dtw, dtwc, n3, xpw, xpwc, n4);
    }

    // 1) in_proj: xz = hs * w_in^T   (bf16x3)
    mma_gemm_bf3<<<dim3(EI/256, ML/128), dim3(512), bsmem>>>(
        ML, EI, DM, hsh, hsl, DM, wih, wil, DM, xz, EI);

    // 2) depthwise conv + silu (exact xc + tf32 xcr)
    conv_silu_kernel<<<dim3(DI/256, L_/CLC, B_), t256>>>(xz, convw, convb, xc, xcr);

    // 3a) x_proj B/C (fp32 split-K x8)
    sgemm_splitk_kernel<64,32,16,4,2><<<dim3(KS_BC, ML/64), t256>>>(
        ML, 32, DI/KS_BC, xc, DI, xpw + (size_t)DTR*DI, DI, bcp, 32);

    // 3b) x_proj dt_lo (tf32 mma split-K x4)
    mma_gemm<0,1><<<dim3(KS_DT, ML/128), t256, msmem>>>(
        ML, DTR, DI/KS_DT, xcr, DI, xpwc, DI, dtlp, DTR, nullptr);

    // 3c) reduce split-K partials (bc exact, dtlo tf32-rounded)
    {
        const size_t nt = (size_t)ML*32/4 + (size_t)ML*DTR/4;
        reduce_splitk_kernel<<<(unsigned)((nt+255)/256), t256>>>(bcp, bc, dtlp, dtlo);
    }

    // 4) dt_proj + softplus (tf32 mma)
    mma_gemm<1,0><<<dim3(DI/128, ML/128), t256, msmem>>>(
        ML, DI, DTR, dtlo, DTR, dtwc, DTR, dtb_, DI, dtb);

    // 5) selective scan (emits y as bf16 hi/lo)
    scan_kernel<<<dim3(DI/32, B_), dim3(128)>>>(
        xz, xc, dtb_, bc, Alog, Dp, yh, yl);

    // 6) out_proj: out = y * outw^T   (bf16x3)
    mma_gemm_bf3<<<dim3(DM/256, ML/128), dim3(512), bsmem>>>(
        ML, DM, DI, yh, yl, DI, owh, owl, DI, out, DM);
}

// round 15
// speedup vs baseline: 1.3301x; 1.3301x over previous
#include <cuda_runtime.h>
#include <cstdint>
#include <cstddef>

// ---------------- problem constants ----------------
#define B_   2
#define L_   2048
#define DM   2048          // d_model
#define DI   4096          // d_inner
#define EI   8192          // 2*d_inner
#define DS   16            // d_state
#define DTR  128           // dt_rank
#define XD   160           // dt_rank + 2*d_state
#define ML   (B_*L_)       // 4096 rows

#define KS_BC 8            // split-K for B/C sgemm
#define KS_DT 4            // split-K for dt_lo mma

// ---------------- scratch (device globals; no allocation allowed) ----------------
__device__ float g_xz  [(size_t)ML * EI];
__device__ float g_xc  [(size_t)ML * DI];   // conv+silu (exact fp32)
__device__ float g_xcr [(size_t)ML * DI];   // conv+silu (tf32-rounded)
__device__ float g_bc  [(size_t)ML * 32];   // B(16) + C(16) per row, fp32
__device__ float g_bcp [(size_t)KS_BC * ML * 32];   // split-K partials
__device__ float g_dt  [(size_t)ML * DI];
__device__ float g_y   [(size_t)ML * DI];   // scan output (tf32-rounded)
__device__ float g_hsc [(size_t)ML * DM];   // tf32-rounded hidden_states
__device__ float g_winc[(size_t)EI * DM];   // tf32-rounded in_proj_weight
__device__ float g_dtwc[(size_t)DI * DTR];  // tf32-rounded dt_proj_weight
__device__ float g_outwc[(size_t)DM * DI];  // tf32-rounded out_proj_weight
__device__ float g_xpwc[(size_t)DTR * DI];  // tf32-rounded x_proj_weight rows 0..127
__device__ float g_dtlo[(size_t)ML * DTR];  // tf32 dt_lo (compact)
__device__ float g_dtlp[(size_t)KS_DT * ML * DTR];  // split-K partials

__device__ __forceinline__ unsigned f2tf32(float f) {
    unsigned u;
    asm("cvt.rna.tf32.f32 %0, %1;" : "=r"(u) : "f"(f));
    return u;
}
__device__ __forceinline__ float tf32r(float f) {
    return __uint_as_float(f2tf32(f));
}

// ---------------- fused tf32 rounding: 5 segments in one launch ----------------
__global__ __launch_bounds__(256)
void round_all_kernel(const float* s0, float* d0, size_t n0,
                      const float* s1, float* d1, size_t n1,
                      const float* s2, float* d2, size_t n2,
                      const float* s3, float* d3, size_t n3,
                      const float* s4, float* d4, size_t n4)
{
    size_t i = (size_t)blockIdx.x * blockDim.x + threadIdx.x;
    const float* s; float* d;
    if (i < n0) { s = s0; d = d0; }
    else if ((i -= n0) < n1) { s = s1; d = d1; }
    else if ((i -= n1) < n2) { s = s2; d = d2; }
    else if ((i -= n2) < n3) { s = s3; d = d3; }
    else if ((i -= n3) < n4) { s = s4; d = d4; }
    else return;
    float4 v = ((const float4*)s)[i];
    v.x = tf32r(v.x); v.y = tf32r(v.y); v.z = tf32r(v.z); v.w = tf32r(v.w);
    ((float4*)d)[i] = v;
}

// ---------------- split-K reduce: bc (8 partials) + dtlo (4 partials, tf32r) ----------------
__global__ __launch_bounds__(256)
void reduce_splitk_kernel(const float* __restrict__ bcp, float* __restrict__ bc,
                          const float* __restrict__ dtlp, float* __restrict__ dtlo)
{
    const size_t nBC = (size_t)ML * 32 / 4;
    const size_t nDT = (size_t)ML * DTR / 4;
    size_t i = (size_t)blockIdx.x * blockDim.x + threadIdx.x;
    if (i < nBC) {
        float4 a = ((const float4*)bcp)[i];
        #pragma unroll
        for (int s = 1; s < KS_BC; s++) {
            float4 p = ((const float4*)(bcp + (size_t)s * ML * 32))[i];
            a.x += p.x; a.y += p.y; a.z += p.z; a.w += p.w;
        }
        ((float4*)bc)[i] = a;
    } else if ((i -= nBC) < nDT) {
        float4 a = ((const float4*)dtlp)[i];
        #pragma unroll
        for (int s = 1; s < KS_DT; s++) {
            float4 p = ((const float4*)(dtlp + (size_t)s * ML * DTR))[i];
            a.x += p.x; a.y += p.y; a.z += p.z; a.w += p.w;
        }
        a.x = tf32r(a.x); a.y = tf32r(a.y); a.z = tf32r(a.z); a.w = tf32r(a.w);
        ((float4*)dtlo)[i] = a;
    }
}

// ---------------- async-copy + ldmatrix helpers ----------------
__device__ __forceinline__ void cp16(float* smem_dst, const float* gmem_src) {
    unsigned s = (unsigned)__cvta_generic_to_shared(smem_dst);
    asm volatile("cp.async.cg.shared.global [%0], [%1], 16;\n" :: "r"(s), "l"(gmem_src));
}
__device__ __forceinline__ void cp_commit() {
    asm volatile("cp.async.commit_group;\n");
}
__device__ __forceinline__ void cp_wait1() {
    asm volatile("cp.async.wait_group 1;\n");
}
__device__ __forceinline__ void cp_wait2() {
    asm volatile("cp.async.wait_group 2;\n");
}
__device__ __forceinline__ void ldsm4(unsigned& r0, unsigned& r1, unsigned& r2, unsigned& r3,
                                      unsigned addr) {
    asm volatile("ldmatrix.sync.aligned.m8n8.x4.shared.b16 {%0,%1,%2,%3}, [%4];"
                 : "=r"(r0), "=r"(r1), "=r"(r2), "=r"(r3) : "r"(addr));
}

// =========================================================================
// WIDE TF32 GEMM: BM=128, BN=256, BK=32, 512 threads (16 warps, 2m x 8n),
// warp tile 64x32, 4-stage cp.async (wait_group 2), ldmatrix fragments.
// =========================================================================
#define TSZ_A 4096
#define TSZ_B 8192
#define STB_A 16384u
#define STB_B 32768u

__global__ __launch_bounds__(512, 1)
void mma_gemm_wide(int M, int N, int K,
                   const float* __restrict__ A, int lda,
                   const float* __restrict__ Bw, int ldb,
                   float* __restrict__ C, int ldc)
{
    extern __shared__ float smem[];
    float* As = smem;
    float* Bs = smem + 4*TSZ_A;

    const int tid  = threadIdx.x;
    const int lane = tid & 31;
    const int warp = tid >> 5;
    const int wm   = (warp & 1) * 64;
    const int wn   = (warp >> 1) * 32;
    const int bm   = blockIdx.y * 128;
    const int bn   = blockIdx.x * 256;

    const int q     = tid & 7;
    const int r0    = tid >> 3;
    const int pq    = q ^ (r0 & 7);
    const int dBase = r0*32 + pq*4;

    const float* gA = A  + (size_t)(bm + r0) * lda + q*4;
    const float* gB = Bw + (size_t)(bn + r0) * ldb + q*4;

    const int g    = lane >> 3;
    const int kg   = g >> 1;
    const int sub8 = (g & 1) << 3;
    const int lr   = lane & 7;
    const unsigned aSh = (unsigned)__cvta_generic_to_shared(As);
    const unsigned bSh = (unsigned)__cvta_generic_to_shared(Bs);
    const unsigned aBase  = aSh + (unsigned)(wm + sub8 + lr) * 128;
    const unsigned bBase0 = bSh + (unsigned)(wn + sub8 + lr) * 128;
    const unsigned bBase1 = bBase0 + 16*128;
    unsigned tks[4];
    #pragma unroll
    for (int ks = 0; ks < 4; ks++)
        tks[ks] = (unsigned)(((((ks << 1) + kg) ^ lr) & 7) << 4);

    const int u  = lane >> 2;
    const int li = lane & 3;

    float acc[4][4][4];
    #pragma unroll
    for (int i = 0; i < 4; i++)
        #pragma unroll
        for (int j = 0; j < 4; j++)
            #pragma unroll
            for (int r = 0; r < 4; r++) acc[i][j][r] = 0.0f;

    const int KT = K / 32;

    #pragma unroll
    for (int s = 0; s < 2; s++) {
        const size_t ko = (size_t)s * 32;
        #pragma unroll
        for (int i = 0; i < 2; i++)
            cp16(As + s*TSZ_A + dBase + i*2048, gA + (size_t)i*64*lda + ko);
        #pragma unroll
        for (int i = 0; i < 4; i++)
            cp16(Bs + s*TSZ_B + dBase + i*2048, gB + (size_t)i*64*ldb + ko);
        cp_commit();
    }

    for (int kt = 0; kt < KT; kt++) {
        const int cur = kt & 3;
        if (kt + 2 < KT) {
            const int st = (kt + 2) & 3;
            const size_t ko = (size_t)(kt + 2) * 32;
            #pragma unroll
            for (int i = 0; i < 2; i++)
                cp16(As + st*TSZ_A + dBase + i*2048, gA + (size_t)i*64*lda + ko);
            #pragma unroll
            for (int i = 0; i < 4; i++)
                cp16(Bs + st*TSZ_B + dBase + i*2048, gB + (size_t)i*64*ldb + ko);
        }
        cp_commit();
        cp_wait2();
        __syncthreads();

        const unsigned aOff  = aBase  + (unsigned)cur * STB_A;
        const unsigned bOff0 = bBase0 + (unsigned)cur * STB_B;
        const unsigned bOff1 = bBase1 + (unsigned)cur * STB_B;

        #pragma unroll
        for (int ks = 0; ks < 4; ks++) {
            unsigned af[4][4];
            unsigned bf[4][2];
            #pragma unroll
            for (int i = 0; i < 4; i++)
                ldsm4(af[i][0], af[i][1], af[i][2], af[i][3],
                      aOff + (unsigned)i*2048 + tks[ks]);
            ldsm4(bf[0][0], bf[1][0], bf[0][1], bf[1][1], bOff0 + tks[ks]);
            ldsm4(bf[2][0], bf[3][0], bf[2][1], bf[3][1], bOff1 + tks[ks]);

            #pragma unroll
            for (int i = 0; i < 4; i++)
                #pragma unroll
                for (int j = 0; j < 4; j++) {
                    asm volatile(
                        "mma.sync.aligned.m16n8k8.row.col.f32.tf32.tf32.f32 "
                        "{%0,%1,%2,%3}, {%4,%5,%6,%7}, {%8,%9}, {%0,%1,%2,%3};"
                        : "+f"(acc[i][j][0]), "+f"(acc[i][j][1]),
                          "+f"(acc[i][j][2]), "+f"(acc[i][j][3])
                        : "r"(af[i][0]), "r"(af[i][1]), "r"(af[i][2]), "r"(af[i][3]),
                          "r"(bf[j][0]), "r"(bf[j][1]));
                }
        }
    }

    #pragma unroll
    for (int i = 0; i < 4; i++) {
        const int r0e = bm + wm + i*16 + u;
        #pragma unroll
        for (int j = 0; j < 4; j++) {
            const int c0 = bn + wn + j*8 + li*2;
            *(float2*)&C[(size_t)r0e * ldc + c0]     = make_float2(acc[i][j][0], acc[i][j][1]);
            *(float2*)&C[(size_t)(r0e+8) * ldc + c0] = make_float2(acc[i][j][2], acc[i][j][3]);
        }
    }
}

// ================= mma.sync TF32 GEMM BN=128 =================
// EPI: 0 = none, 1 = softplus(v+bias[n])
// SPLITK: blockIdx.x = k-split index (N must be 128); partial -> C + split*M*ldc
#define TSZ32 4096
#define STB   16384u

template<int EPI, int SPLITK>
__global__ __launch_bounds__(256, 2)
void mma_gemm(int M, int N, int K,
              const float* __restrict__ A, int lda,
              const float* __restrict__ Bw, int ldb,
              float* __restrict__ C, int ldc,
              const float* __restrict__ bias)
{
    extern __shared__ float smem[];
    float* As = smem;
    float* Bs = smem + 3*TSZ32;

    const int tid  = threadIdx.x;
    const int lane = tid & 31;
    const int warp = tid >> 5;
    const int wm   = (warp & 1) * 64;
    const int wn   = (warp >> 1) * 32;
    const int bm   = blockIdx.y * 128;
    int bn = 0;
    if (SPLITK) {
        const int sk = blockIdx.x;
        A  += (size_t)sk * K;
        Bw += (size_t)sk * K;
        C  += (size_t)sk * M * ldc;
    } else {
        bn = blockIdx.x * 128;
    }

    const int q     = tid & 7;
    const int r0    = tid >> 3;
    const int pq    = q ^ (r0 & 7);
    const int dBase = r0*32 + pq*4;

    const float* gA = A  + (size_t)(bm + r0) * lda + q*4;
    const float* gB = Bw + (size_t)(bn + r0) * ldb + q*4;

    const int g    = lane >> 3;
    const int kg   = g >> 1;
    const int sub8 = (g & 1) << 3;
    const int lr   = lane & 7;
    const unsigned aSh = (unsigned)__cvta_generic_to_shared(As);
    const unsigned bSh = (unsigned)__cvta_generic_to_shared(Bs);
    const unsigned aBase  = aSh + (unsigned)(wm + sub8 + lr) * 128;
    const unsigned bBase0 = bSh + (unsigned)(wn + sub8 + lr) * 128;
    const unsigned bBase1 = bBase0 + 16*128;
    unsigned tks[4];
    #pragma unroll
    for (int ks = 0; ks < 4; ks++)
        tks[ks] = (unsigned)(((((ks << 1) + kg) ^ lr) & 7) << 4);

    const int u  = lane >> 2;
    const int li = lane & 3;

    float acc[4][4][4];
    #pragma unroll
    for (int i = 0; i < 4; i++)
        #pragma unroll
        for (int j = 0; j < 4; j++)
            #pragma unroll
            for (int r = 0; r < 4; r++) acc[i][j][r] = 0.0f;

    const int KT = K / 32;

    #pragma unroll
    for (int s = 0; s < 2; s++) {
        const size_t ko = (size_t)s * 32;
        #pragma unroll
        for (int i = 0; i < 4; i++) {
            cp16(As + s*TSZ32 + dBase + i*1024, gA + (size_t)i*32*lda + ko);
            cp16(Bs + s*TSZ32 + dBase + i*1024, gB + (size_t)i*32*ldb + ko);
        }
        cp_commit();
    }
    cp_wait1();
    __syncthreads();

    for (int kt = 0; kt < KT; kt++) {
        const int cur = kt % 3;
        if (kt + 2 < KT) {
            const int st = (kt + 2) % 3;
            const size_t ko = (size_t)(kt + 2) * 32;
            #pragma unroll
            for (int i = 0; i < 4; i++) {
                cp16(As + st*TSZ32 + dBase + i*1024, gA + (size_t)i*32*lda + ko);
                cp16(Bs + st*TSZ32 + dBase + i*1024, gB + (size_t)i*32*ldb + ko);
            }
        }
        cp_commit();

        const unsigned aOff  = aBase  + (unsigned)cur * STB;
        const unsigned bOff0 = bBase0 + (unsigned)cur * STB;
        const unsigned bOff1 = bBase1 + (unsigned)cur * STB;

        #pragma unroll
        for (int ks = 0; ks < 4; ks++) {
            unsigned af[4][4];
            unsigned bf[4][2];
            #pragma unroll
            for (int i = 0; i < 4; i++)
                ldsm4(af[i][0], af[i][1], af[i][2], af[i][3],
                      aOff + (unsigned)i*2048 + tks[ks]);
            ldsm4(bf[0][0], bf[1][0], bf[0][1], bf[1][1], bOff0 + tks[ks]);
            ldsm4(bf[2][0], bf[3][0], bf[2][1], bf[3][1], bOff1 + tks[ks]);

            #pragma unroll
            for (int i = 0; i < 4; i++)
                #pragma unroll
                for (int j = 0; j < 4; j++) {
                    asm volatile(
                        "mma.sync.aligned.m16n8k8.row.col.f32.tf32.tf32.f32 "
                        "{%0,%1,%2,%3}, {%4,%5,%6,%7}, {%8,%9}, {%0,%1,%2,%3};"
                        : "+f"(acc[i][j][0]), "+f"(acc[i][j][1]),
                          "+f"(acc[i][j][2]), "+f"(acc[i][j][3])
                        : "r"(af[i][0]), "r"(af[i][1]), "r"(af[i][2]), "r"(af[i][3]),
                          "r"(bf[j][0]), "r"(bf[j][1]));
                }
        }

        cp_wait1();
        __syncthreads();
    }

    #pragma unroll
    for (int i = 0; i < 4; i++) {
        const int r0e = bm + wm + i*16 + u;
        #pragma unroll
        for (int j = 0; j < 4; j++) {
            const int c0 = bn + wn + j*8 + li*2;
            float v0 = acc[i][j][0], v1 = acc[i][j][1];
            float v2 = acc[i][j][2], v3 = acc[i][j][3];
            if (EPI == 1) {
                const float bA = bias[c0], bB = bias[c0+1];
                v0 += bA; v1 += bB; v2 += bA; v3 += bB;
                v0 = (v0 > 20.0f) ? v0 : log1pf(__expf(v0));
                v1 = (v1 > 20.0f) ? v1 : log1pf(__expf(v1));
                v2 = (v2 > 20.0f) ? v2 : log1pf(__expf(v2));
                v3 = (v3 > 20.0f) ? v3 : log1pf(__expf(v3));
            }
            *(float2*)&C[(size_t)r0e * ldc + c0]     = make_float2(v0, v1);
            *(float2*)&C[(size_t)(r0e+8) * ldc + c0] = make_float2(v2, v3);
        }
    }
}

// ---------------- fp32 tiled SGEMM, split-K (B/C part of x_proj: N=32) ----------------
template<int BM, int BN, int BK, int TM, int TN>
__global__ __launch_bounds__(256)
void sgemm_splitk_kernel(int M, int N, int KC,
                         const float* __restrict__ A, int lda,
                         const float* __restrict__ Bw, int ldb,
                         float* __restrict__ C, int ldc)
{
    __shared__ float As[BK][BM];
    __shared__ float Bs[BK][BN];

    const int tid = threadIdx.x;
    const int tx  = tid & 15;
    const int ty  = tid >> 4;
    const int bm  = blockIdx.y * BM;
    const int sk  = blockIdx.x;
    const size_t k0base = (size_t)sk * KC;
    C += (size_t)sk * M * ldc;

    float acc[TM][TN];
    #pragma unroll
    for (int i = 0; i < TM; i++)
        #pragma unroll
        for (int j = 0; j < TN; j++) acc[i][j] = 0.0f;

    const int a_m = tid / (BK/4);
    const int a_k = (tid % (BK/4)) * 4;

    for (int k0 = 0; k0 < KC; k0 += BK) {
        if (tid < (BM*BK/4)) {
            float4 v = *(const float4*)&A[(size_t)(bm + a_m)*lda + k0base + k0 + a_k];
            As[a_k+0][a_m] = v.x; As[a_k+1][a_m] = v.y;
            As[a_k+2][a_m] = v.z; As[a_k+3][a_m] = v.w;
        }
        if (tid < (BN*BK/4)) {
            float4 v = *(const float4*)&Bw[(size_t)a_m*ldb + k0base + k0 + a_k];
            Bs[a_k+0][a_m] = v.x; Bs[a_k+1][a_m] = v.y;
            Bs[a_k+2][a_m] = v.z; Bs[a_k+3][a_m] = v.w;
        }
        __syncthreads();

        #pragma unroll
        for (int k = 0; k < BK; k++) {
            float rm[TM], rn[TN];
            #pragma unroll
            for (int i = 0; i < TM; i++) rm[i] = As[k][ty*TM + i];
            #pragma unroll
            for (int j = 0; j < TN; j++) rn[j] = Bs[k][tx*TN + j];
            #pragma unroll
            for (int i = 0; i < TM; i++)
                #pragma unroll
                for (int j = 0; j < TN; j++)
                    acc[i][j] += rm[i] * rn[j];
        }
        __syncthreads();
    }

    #pragma unroll
    for (int i = 0; i < TM; i++) {
        const int m = bm + ty*TM + i;
        #pragma unroll
        for (int j = 0; j < TN; j++) {
            const int n = tx*TN + j;
            C[(size_t)m*ldc + n] = acc[i][j];
        }
    }
}

// ---------------- depthwise causal conv(k=4) + bias + silu, L-chunked ----------------
#define CLC 64
__global__ __launch_bounds__(256)
void conv_silu_kernel(const float* __restrict__ xz,
                      const float* __restrict__ w,
                      const float* __restrict__ bias,
                      float* __restrict__ xc,
                      float* __restrict__ xcr)
{
    const int d  = blockIdx.x * blockDim.x + threadIdx.x;
    const int b  = blockIdx.z;
    const int l0 = blockIdx.y * CLC;

    const float w0 = w[d*4+0], w1 = w[d*4+1], w2 = w[d*4+2], w3 = w[d*4+3];
    const float bi = bias[d];
    const float* px = xz  + ((size_t)b * L_ + l0) * EI + d;
    float*       po = xc  + ((size_t)b * L_ + l0) * DI + d;
    float*       pr = xcr + ((size_t)b * L_ + l0) * DI + d;

    float x0 = 0.f, x1 = 0.f, x2 = 0.f;
    if (l0 > 0) {
        x0 = px[-(size_t)3 * EI];
        x1 = px[-(size_t)2 * EI];
        x2 = px[-(size_t)1 * EI];
    }
    #pragma unroll 4
    for (int l = 0; l < CLC; l++) {
        float x3 = px[(size_t)l * EI];
        float v  = w0*x0 + w1*x1 + w2*x2 + w3*x3 + bi;
        v = v / (1.0f + __expf(-v));
        po[(size_t)l * DI] = v;
        pr[(size_t)l * DI] = tf32r(v);
        x0 = x1; x1 = x2; x2 = x3;
    }
}

// ---------------- selective scan: state-parallel + cp.async smem staging ----------------
// 128 threads = 32 channels x 4 state-lanes. Chunks of SCH=32 timesteps double-
// buffered in smem; prefetch distance = 1 chunk (~1280 compute cycles).
#define SCH 32
__global__ __launch_bounds__(128)
void scan_kernel(const float* __restrict__ xz,
                 const float* __restrict__ xc,
                 const float* __restrict__ dt,
                 const float* __restrict__ bc,
                 const float* __restrict__ A_log,
                 const float* __restrict__ Dp,
                 float* __restrict__ y)
{
    __shared__ float s_dt[2][SCH][32];
    __shared__ float s_xc[2][SCH][32];
    __shared__ float s_z [2][SCH][32];
    __shared__ float s_bc[2][SCH][32];

    const int b    = blockIdx.y;
    const int tid  = threadIdx.x;
    const int wid  = tid >> 5;
    const int lane = tid & 31;
    const int sub  = lane & 3;
    const int cidx = wid * 8 + (lane >> 2);
    const int d0   = blockIdx.x * 32;
    const int d    = d0 + cidx;

    // loader mapping: 2 cp16 per array per chunk (rows lrow and lrow+16)
    const int lrow = tid >> 3;                       // 0..15
    const int lcol = (tid & 7) * 4;                  // 0,4,..28

    float negA[4];
    #pragma unroll
    for (int j = 0; j < 4; j++)
        negA[j] = -__expf(A_log[d*DS + sub*4 + j]);
    const float negA0 = -__expf(A_log[d*DS]);

    bool chain = (negA0 != 0.0f);
    #pragma unroll
    for (int n = 1; n < DS; n++) {
        float na = -__expf(A_log[d*DS + n]);
        float r  = na - (float)(n+1) * negA0;
        if (fabsf(r) > 1e-4f * fabsf(na)) chain = false;
    }

    const float Dd = Dp[d];
    float h[4] = {0.f, 0.f, 0.f, 0.f};

    const size_t rb = (size_t)b * L_;
    const float* pdt = dt + rb * DI;
    const float* pxc = xc + rb * DI;
    const float* pz  = xz + rb * EI + DI;
    const float* pbc = bc + rb * 32;
    float*       py  = y  + rb * DI + d;

    // issue chunks 0 and 1
    #pragma unroll
    for (int c = 0; c < 2; c++) {
        const size_t l0 = (size_t)c * SCH;
        #pragma unroll
        for (int rr = 0; rr < 2; rr++) {
            const int row = lrow + rr*16;
            cp16(&s_dt[c][row][lcol], pdt + (l0 + row) * DI + d0 + lcol);
            cp16(&s_xc[c][row][lcol], pxc + (l0 + row) * DI + d0 + lcol);
            cp16(&s_z [c][row][lcol], pz  + (l0 + row) * EI + d0 + lcol);
            cp16(&s_bc[c][row][lcol], pbc + (l0 + row) * 32 + lcol);
        }
        cp_commit();
    }
    cp_wait1();
    __syncthreads();

    const int NCH = L_ / SCH;
    for (int c = 0; c < NCH; c++) {
        const int buf = c & 1;

        #pragma unroll 4
        for (int i = 0; i < SCH; i++) {
            const float dtv = s_dt[buf][i][cidx];
            const float xv  = s_xc[buf][i][cidx];
            const float zv  = s_z [buf][i][cidx];
            const float bc0 = s_bc[buf][i][lane];

            float dA[4];
            if (chain) {
                const float b1 = __expf(dtv * negA0);
                const float b2 = b1*b1, b3 = b2*b1, b4 = b2*b2;
                const float b8 = b4*b4, b12 = b8*b4;
                const float pw = (sub == 0) ? 1.0f : (sub == 1) ? b4 : (sub == 2) ? b8 : b12;
                dA[0] = pw*b1; dA[1] = pw*b2; dA[2] = pw*b3; dA[3] = pw*b4;
            } else {
                #pragma unroll
                for (int j = 0; j < 4; j++) dA[j] = __expf(dtv * negA[j]);
            }

            const float du = dtv * xv;
            float yp = 0.0f;
            #pragma unroll
            for (int j = 0; j < 4; j++) {
                const float Bn = __shfl_sync(0xFFFFFFFFu, bc0, sub*4 + j);
                const float Cn = __shfl_sync(0xFFFFFFFFu, bc0, 16 + sub*4 + j);
                h[j] = h[j] * dA[j] + du * Bn;
                yp  += h[j] * Cn;
            }
            yp += __shfl_xor_sync(0xFFFFFFFFu, yp, 1);
            yp += __shfl_xor_sync(0xFFFFFFFFu, yp, 2);

            if (sub == 0) {
                const float yv = yp + xv * Dd;
                const float zs = zv / (1.0f + __expf(-zv));
                py[(size_t)(c*SCH + i) * DI] = tf32r(yv * zs);
            }
        }

        __syncthreads();   // all threads done reading buf
        if (c + 2 < NCH) {
            const size_t l0 = (size_t)(c + 2) * SCH;
            #pragma unroll
            for (int rr = 0; rr < 2; rr++) {
                const int row = lrow + rr*16;
                cp16(&s_dt[buf][row][lcol], pdt + (l0 + row) * DI + d0 + lcol);
                cp16(&s_xc[buf][row][lcol], pxc + (l0 + row) * DI + d0 + lcol);
                cp16(&s_z [buf][row][lcol], pz  + (l0 + row) * EI + d0 + lcol);
                cp16(&s_bc[buf][row][lcol], pbc + (l0 + row) * 32 + lcol);
            }
        }
        cp_commit();
        cp_wait1();        // chunk c+1 resident
        __syncthreads();
    }
}

// ---------------- launch ----------------
extern "C" void kernel_launch(void* const* d_in, const int* in_sizes, int n_in,
                              void* d_out, int out_size)
{
    const float* hs    = (const float*)d_in[0];
    const float* w_in  = (const float*)d_in[1];
    const float* convw = (const float*)d_in[2];
    const float* convb = (const float*)d_in[3];
    const float* xpw   = (const float*)d_in[4];
    const float* dtw   = (const float*)d_in[5];
    const float* dtb   = (const float*)d_in[6];
    const float* outw  = (const float*)d_in[7];
    const float* Alog  = (const float*)d_in[8];
    const float* Dp    = (const float*)d_in[9];
    float*       out   = (float*)d_out;

    float *xz, *xc, *xcr, *bc, *bcp, *dtb_, *yb;
    float *hsc, *winc, *dtwc, *outwc, *xpwc, *dtlo, *dtlp;
    cudaGetSymbolAddress((void**)&xz,    g_xz);
    cudaGetSymbolAddress((void**)&xc,    g_xc);
    cudaGetSymbolAddress((void**)&xcr,   g_xcr);
    cudaGetSymbolAddress((void**)&bc,    g_bc);
    cudaGetSymbolAddress((void**)&bcp,   g_bcp);
    cudaGetSymbolAddress((void**)&dtb_,  g_dt);
    cudaGetSymbolAddress((void**)&yb,    g_y);
    cudaGetSymbolAddress((void**)&hsc,   g_hsc);
    cudaGetSymbolAddress((void**)&winc,  g_winc);
    cudaGetSymbolAddress((void**)&dtwc,  g_dtwc);
    cudaGetSymbolAddress((void**)&outwc, g_outwc);
    cudaGetSymbolAddress((void**)&xpwc,  g_xpwc);
    cudaGetSymbolAddress((void**)&dtlo,  g_dtlo);
    cudaGetSymbolAddress((void**)&dtlp,  g_dtlp);

    const dim3 t256(256);
    const size_t msmem = 6 * TSZ32 * sizeof(float);
    const size_t wsmem = 4 * (TSZ_A + TSZ_B) * sizeof(float);

    cudaFuncSetAttribute((const void*)&mma_gemm<1,0>, cudaFuncAttributeMaxDynamicSharedMemorySize, (int)msmem);
    cudaFuncSetAttribute((const void*)&mma_gemm<0,1>, cudaFuncAttributeMaxDynamicSharedMemorySize, (int)msmem);
    cudaFuncSetAttribute((const void*)&mma_gemm_wide, cudaFuncAttributeMaxDynamicSharedMemorySize, (int)wsmem);

    // 0) fused tf32 pre-rounding
    {
        const size_t n0 = (size_t)ML*DM/4, n1 = (size_t)EI*DM/4,
                     n2 = (size_t)DI*DTR/4, n3 = (size_t)DM*DI/4,
                     n4 = (size_t)DTR*DI/4;
        const size_t nt = n0 + n1 + n2 + n3 + n4;
        round_all_kernel<<<(unsigned)((nt+255)/256), t256>>>(
            hs, hsc, n0, w_in, winc, n1, dtw, dtwc, n2, outw, outwc, n3, xpw, xpwc, n4);
    }

    // 1) in_proj (wide tf32 mma)
    mma_gemm_wide<<<dim3(EI/256, ML/128), dim3(512), wsmem>>>(
        ML, EI, DM, hsc, DM, winc, DM, xz, EI);

    // 2) depthwise conv + silu
    conv_silu_kernel<<<dim3(DI/256, L_/CLC, B_), t256>>>(xz, convw, convb, xc, xcr);

    // 3a) x_proj B/C (fp32 split-K x8)
    sgemm_splitk_kernel<64,32,16,4,2><<<dim3(KS_BC, ML/64), t256>>>(
        ML, 32, DI/KS_BC, xc, DI, xpw + (size_t)DTR*DI, DI, bcp, 32);

    // 3b) x_proj dt_lo (tf32 mma split-K x4)
    mma_gemm<0,1><<<dim3(KS_DT, ML/128), t256, msmem>>>(
        ML, DTR, DI/KS_DT, xcr, DI, xpwc, DI, dtlp, DTR, nullptr);

    // 3c) reduce split-K partials
    {
        const size_t nt = (size_t)ML*32/4 + (size_t)ML*DTR/4;
        reduce_splitk_kernel<<<(unsigned)((nt+255)/256), t256>>>(bcp, bc, dtlp, dtlo);
    }

    // 4) dt_proj + softplus (tf32 mma)
    mma_gemm<1,0><<<dim3(DI/128, ML/128), t256, msmem>>>(
        ML, DI, DTR, dtlo, DTR, dtwc, DTR, dtb_, DI, dtb);

    // 5) selective scan (state-parallel, cp.async staged, SCH=32)
    scan_kernel<<<dim3(DI/32, B_), dim3(128)>>>(
        xz, xc, dtb_, bc, Alog, Dp, yb);

    // 6) out_proj (wide tf32 mma)
    mma_gemm_wide<<<dim3(DM/256, ML/128), dim3(512), wsmem>>>(
        ML, DM, DI, yb, DI, outwc, DI, out, DM);
}

// round 16
// speedup vs baseline: 1.3340x; 1.0029x over previous
#include <cuda_runtime.h>
#include <cstdint>
#include <cstddef>

// ---------------- problem constants ----------------
#define B_   2
#define L_   2048
#define DM   2048          // d_model
#define DI   4096          // d_inner
#define EI   8192          // 2*d_inner
#define DS   16            // d_state
#define DTR  128           // dt_rank
#define XD   160           // dt_rank + 2*d_state
#define ML   (B_*L_)       // 4096 rows

#define KS_BC 8            // split-K for B/C sgemm
#define KS_DT 8            // split-K for dt_lo mma

// ---------------- scratch (device globals; no allocation allowed) ----------------
__device__ float g_xz  [(size_t)ML * EI];
__device__ float g_xc  [(size_t)ML * DI];   // conv+silu (exact fp32)
__device__ float g_xcr [(size_t)ML * DI];   // conv+silu (tf32-rounded)
__device__ float g_bc  [(size_t)ML * 32];   // B(16) + C(16) per row, fp32
__device__ float g_bcp [(size_t)KS_BC * ML * 32];   // split-K partials
__device__ float g_dt  [(size_t)ML * DI];
__device__ float g_y   [(size_t)ML * DI];   // scan output (tf32-rounded)
__device__ float g_hsc [(size_t)ML * DM];   // tf32-rounded hidden_states
__device__ float g_winc[(size_t)EI * DM];   // tf32-rounded in_proj_weight
__device__ float g_dtwc[(size_t)DI * DTR];  // tf32-rounded dt_proj_weight
__device__ float g_outwc[(size_t)DM * DI];  // tf32-rounded out_proj_weight
__device__ float g_xpwc[(size_t)DTR * DI];  // tf32-rounded x_proj_weight rows 0..127
__device__ float g_dtlo[(size_t)ML * DTR];  // tf32 dt_lo (compact)
__device__ float g_dtlp[(size_t)KS_DT * ML * DTR];  // split-K partials

__device__ __forceinline__ unsigned f2tf32(float f) {
    unsigned u;
    asm("cvt.rna.tf32.f32 %0, %1;" : "=r"(u) : "f"(f));
    return u;
}
__device__ __forceinline__ float tf32r(float f) {
    return __uint_as_float(f2tf32(f));
}

// ---------------- fused tf32 rounding: 5 segments in one launch ----------------
__global__ __launch_bounds__(256)
void round_all_kernel(const float* s0, float* d0, size_t n0,
                      const float* s1, float* d1, size_t n1,
                      const float* s2, float* d2, size_t n2,
                      const float* s3, float* d3, size_t n3,
                      const float* s4, float* d4, size_t n4)
{
    size_t i = (size_t)blockIdx.x * blockDim.x + threadIdx.x;
    const float* s; float* d;
    if (i < n0) { s = s0; d = d0; }
    else if ((i -= n0) < n1) { s = s1; d = d1; }
    else if ((i -= n1) < n2) { s = s2; d = d2; }
    else if ((i -= n2) < n3) { s = s3; d = d3; }
    else if ((i -= n3) < n4) { s = s4; d = d4; }
    else return;
    float4 v = ((const float4*)s)[i];
    v.x = tf32r(v.x); v.y = tf32r(v.y); v.z = tf32r(v.z); v.w = tf32r(v.w);
    ((float4*)d)[i] = v;
}

// ---------------- split-K reduce: bc (8 partials) + dtlo (8 partials, tf32r) ----------------
__global__ __launch_bounds__(256)
void reduce_splitk_kernel(const float* __restrict__ bcp, float* __restrict__ bc,
                          const float* __restrict__ dtlp, float* __restrict__ dtlo)
{
    const size_t nBC = (size_t)ML * 32 / 4;
    const size_t nDT = (size_t)ML * DTR / 4;
    size_t i = (size_t)blockIdx.x * blockDim.x + threadIdx.x;
    if (i < nBC) {
        float4 a = ((const float4*)bcp)[i];
        #pragma unroll
        for (int s = 1; s < KS_BC; s++) {
            float4 p = ((const float4*)(bcp + (size_t)s * ML * 32))[i];
            a.x += p.x; a.y += p.y; a.z += p.z; a.w += p.w;
        }
        ((float4*)bc)[i] = a;
    } else if ((i -= nBC) < nDT) {
        float4 a = ((const float4*)dtlp)[i];
        #pragma unroll
        for (int s = 1; s < KS_DT; s++) {
            float4 p = ((const float4*)(dtlp + (size_t)s * ML * DTR))[i];
            a.x += p.x; a.y += p.y; a.z += p.z; a.w += p.w;
        }
        a.x = tf32r(a.x); a.y = tf32r(a.y); a.z = tf32r(a.z); a.w = tf32r(a.w);
        ((float4*)dtlo)[i] = a;
    }
}

// ---------------- async-copy + ldmatrix helpers ----------------
__device__ __forceinline__ void cp16(float* smem_dst, const float* gmem_src) {
    unsigned s = (unsigned)__cvta_generic_to_shared(smem_dst);
    asm volatile("cp.async.cg.shared.global [%0], [%1], 16;\n" :: "r"(s), "l"(gmem_src));
}
__device__ __forceinline__ void cp_commit() {
    asm volatile("cp.async.commit_group;\n");
}
__device__ __forceinline__ void cp_wait1() {
    asm volatile("cp.async.wait_group 1;\n");
}
__device__ __forceinline__ void cp_wait2() {
    asm volatile("cp.async.wait_group 2;\n");
}
__device__ __forceinline__ void ldsm4(unsigned& r0, unsigned& r1, unsigned& r2, unsigned& r3,
                                      unsigned addr) {
    asm volatile("ldmatrix.sync.aligned.m8n8.x4.shared.b16 {%0,%1,%2,%3}, [%4];"
                 : "=r"(r0), "=r"(r1), "=r"(r2), "=r"(r3) : "r"(addr));
}

// =========================================================================
// WIDE TF32 GEMM: BM=128, BN=256, BK=32, 512 threads (16 warps, 2m x 8n),
// warp tile 64x32, 4-stage cp.async (wait_group 2), ldmatrix fragments.
// =========================================================================
#define TSZ_A 4096
#define TSZ_B 8192
#define STB_A 16384u
#define STB_B 32768u

__global__ __launch_bounds__(512, 1)
void mma_gemm_wide(int M, int N, int K,
                   const float* __restrict__ A, int lda,
                   const float* __restrict__ Bw, int ldb,
                   float* __restrict__ C, int ldc)
{
    extern __shared__ float smem[];
    float* As = smem;
    float* Bs = smem + 4*TSZ_A;

    const int tid  = threadIdx.x;
    const int lane = tid & 31;
    const int warp = tid >> 5;
    const int wm   = (warp & 1) * 64;
    const int wn   = (warp >> 1) * 32;
    const int bm   = blockIdx.y * 128;
    const int bn   = blockIdx.x * 256;

    const int q     = tid & 7;
    const int r0    = tid >> 3;
    const int pq    = q ^ (r0 & 7);
    const int dBase = r0*32 + pq*4;

    const float* gA = A  + (size_t)(bm + r0) * lda + q*4;
    const float* gB = Bw + (size_t)(bn + r0) * ldb + q*4;

    const int g    = lane >> 3;
    const int kg   = g >> 1;
    const int sub8 = (g & 1) << 3;
    const int lr   = lane & 7;
    const unsigned aSh = (unsigned)__cvta_generic_to_shared(As);
    const unsigned bSh = (unsigned)__cvta_generic_to_shared(Bs);
    const unsigned aBase  = aSh + (unsigned)(wm + sub8 + lr) * 128;
    const unsigned bBase0 = bSh + (unsigned)(wn + sub8 + lr) * 128;
    const unsigned bBase1 = bBase0 + 16*128;
    unsigned tks[4];
    #pragma unroll
    for (int ks = 0; ks < 4; ks++)
        tks[ks] = (unsigned)(((((ks << 1) + kg) ^ lr) & 7) << 4);

    const int u  = lane >> 2;
    const int li = lane & 3;

    float acc[4][4][4];
    #pragma unroll
    for (int i = 0; i < 4; i++)
        #pragma unroll
        for (int j = 0; j < 4; j++)
            #pragma unroll
            for (int r = 0; r < 4; r++) acc[i][j][r] = 0.0f;

    const int KT = K / 32;

    #pragma unroll
    for (int s = 0; s < 2; s++) {
        const size_t ko = (size_t)s * 32;
        #pragma unroll
        for (int i = 0; i < 2; i++)
            cp16(As + s*TSZ_A + dBase + i*2048, gA + (size_t)i*64*lda + ko);
        #pragma unroll
        for (int i = 0; i < 4; i++)
            cp16(Bs + s*TSZ_B + dBase + i*2048, gB + (size_t)i*64*ldb + ko);
        cp_commit();
    }

    for (int kt = 0; kt < KT; kt++) {
        const int cur = kt & 3;
        if (kt + 2 < KT) {
            const int st = (kt + 2) & 3;
            const size_t ko = (size_t)(kt + 2) * 32;
            #pragma unroll
            for (int i = 0; i < 2; i++)
                cp16(As + st*TSZ_A + dBase + i*2048, gA + (size_t)i*64*lda + ko);
            #pragma unroll
            for (int i = 0; i < 4; i++)
                cp16(Bs + st*TSZ_B + dBase + i*2048, gB + (size_t)i*64*ldb + ko);
        }
        cp_commit();
        cp_wait2();
        __syncthreads();

        const unsigned aOff  = aBase  + (unsigned)cur * STB_A;
        const unsigned bOff0 = bBase0 + (unsigned)cur * STB_B;
        const unsigned bOff1 = bBase1 + (unsigned)cur * STB_B;

        #pragma unroll
        for (int ks = 0; ks < 4; ks++) {
            unsigned af[4][4];
            unsigned bf[4][2];
            #pragma unroll
            for (int i = 0; i < 4; i++)
                ldsm4(af[i][0], af[i][1], af[i][2], af[i][3],
                      aOff + (unsigned)i*2048 + tks[ks]);
            ldsm4(bf[0][0], bf[1][0], bf[0][1], bf[1][1], bOff0 + tks[ks]);
            ldsm4(bf[2][0], bf[3][0], bf[2][1], bf[3][1], bOff1 + tks[ks]);

            #pragma unroll
            for (int i = 0; i < 4; i++)
                #pragma unroll
                for (int j = 0; j < 4; j++) {
                    asm volatile(
                        "mma.sync.aligned.m16n8k8.row.col.f32.tf32.tf32.f32 "
                        "{%0,%1,%2,%3}, {%4,%5,%6,%7}, {%8,%9}, {%0,%1,%2,%3};"
                        : "+f"(acc[i][j][0]), "+f"(acc[i][j][1]),
                          "+f"(acc[i][j][2]), "+f"(acc[i][j][3])
                        : "r"(af[i][0]), "r"(af[i][1]), "r"(af[i][2]), "r"(af[i][3]),
                          "r"(bf[j][0]), "r"(bf[j][1]));
                }
        }
    }

    #pragma unroll
    for (int i = 0; i < 4; i++) {
        const int r0e = bm + wm + i*16 + u;
        #pragma unroll
        for (int j = 0; j < 4; j++) {
            const int c0 = bn + wn + j*8 + li*2;
            *(float2*)&C[(size_t)r0e * ldc + c0]     = make_float2(acc[i][j][0], acc[i][j][1]);
            *(float2*)&C[(size_t)(r0e+8) * ldc + c0] = make_float2(acc[i][j][2], acc[i][j][3]);
        }
    }
}

// ================= mma.sync TF32 GEMM BN=128 =================
// EPI: 0 = none, 1 = softplus(v+bias[n])
// SPLITK: blockIdx.x = k-split index (N must be 128); partial -> C + split*M*ldc
#define TSZ32 4096
#define STB   16384u

template<int EPI, int SPLITK>
__global__ __launch_bounds__(256, 2)
void mma_gemm(int M, int N, int K,
              const float* __restrict__ A, int lda,
              const float* __restrict__ Bw, int ldb,
              float* __restrict__ C, int ldc,
              const float* __restrict__ bias)
{
    extern __shared__ float smem[];
    float* As = smem;
    float* Bs = smem + 3*TSZ32;

    const int tid  = threadIdx.x;
    const int lane = tid & 31;
    const int warp = tid >> 5;
    const int wm   = (warp & 1) * 64;
    const int wn   = (warp >> 1) * 32;
    const int bm   = blockIdx.y * 128;
    int bn = 0;
    if (SPLITK) {
        const int sk = blockIdx.x;
        A  += (size_t)sk * K;
        Bw += (size_t)sk * K;
        C  += (size_t)sk * M * ldc;
    } else {
        bn = blockIdx.x * 128;
    }

    const int q     = tid & 7;
    const int r0    = tid >> 3;
    const int pq    = q ^ (r0 & 7);
    const int dBase = r0*32 + pq*4;

    const float* gA = A  + (size_t)(bm + r0) * lda + q*4;
    const float* gB = Bw + (size_t)(bn + r0) * ldb + q*4;

    const int g    = lane >> 3;
    const int kg   = g >> 1;
    const int sub8 = (g & 1) << 3;
    const int lr   = lane & 7;
    const unsigned aSh = (unsigned)__cvta_generic_to_shared(As);
    const unsigned bSh = (unsigned)__cvta_generic_to_shared(Bs);
    const unsigned aBase  = aSh + (unsigned)(wm + sub8 + lr) * 128;
    const unsigned bBase0 = bSh + (unsigned)(wn + sub8 + lr) * 128;
    const unsigned bBase1 = bBase0 + 16*128;
    unsigned tks[4];
    #pragma unroll
    for (int ks = 0; ks < 4; ks++)
        tks[ks] = (unsigned)(((((ks << 1) + kg) ^ lr) & 7) << 4);

    const int u  = lane >> 2;
    const int li = lane & 3;

    float acc[4][4][4];
    #pragma unroll
    for (int i = 0; i < 4; i++)
        #pragma unroll
        for (int j = 0; j < 4; j++)
            #pragma unroll
            for (int r = 0; r < 4; r++) acc[i][j][r] = 0.0f;

    const int KT = K / 32;

    #pragma unroll
    for (int s = 0; s < 2; s++) {
        const size_t ko = (size_t)s * 32;
        #pragma unroll
        for (int i = 0; i < 4; i++) {
            cp16(As + s*TSZ32 + dBase + i*1024, gA + (size_t)i*32*lda + ko);
            cp16(Bs + s*TSZ32 + dBase + i*1024, gB + (size_t)i*32*ldb + ko);
        }
        cp_commit();
    }
    cp_wait1();
    __syncthreads();

    for (int kt = 0; kt < KT; kt++) {
        const int cur = kt % 3;
        if (kt + 2 < KT) {
            const int st = (kt + 2) % 3;
            const size_t ko = (size_t)(kt + 2) * 32;
            #pragma unroll
            for (int i = 0; i < 4; i++) {
                cp16(As + st*TSZ32 + dBase + i*1024, gA + (size_t)i*32*lda + ko);
                cp16(Bs + st*TSZ32 + dBase + i*1024, gB + (size_t)i*32*ldb + ko);
            }
        }
        cp_commit();

        const unsigned aOff  = aBase  + (unsigned)cur * STB;
        const unsigned bOff0 = bBase0 + (unsigned)cur * STB;
        const unsigned bOff1 = bBase1 + (unsigned)cur * STB;

        #pragma unroll
        for (int ks = 0; ks < 4; ks++) {
            unsigned af[4][4];
            unsigned bf[4][2];
            #pragma unroll
            for (int i = 0; i < 4; i++)
                ldsm4(af[i][0], af[i][1], af[i][2], af[i][3],
                      aOff + (unsigned)i*2048 + tks[ks]);
            ldsm4(bf[0][0], bf[1][0], bf[0][1], bf[1][1], bOff0 + tks[ks]);
            ldsm4(bf[2][0], bf[3][0], bf[2][1], bf[3][1], bOff1 + tks[ks]);

            #pragma unroll
            for (int i = 0; i < 4; i++)
                #pragma unroll
                for (int j = 0; j < 4; j++) {
                    asm volatile(
                        "mma.sync.aligned.m16n8k8.row.col.f32.tf32.tf32.f32 "
                        "{%0,%1,%2,%3}, {%4,%5,%6,%7}, {%8,%9}, {%0,%1,%2,%3};"
                        : "+f"(acc[i][j][0]), "+f"(acc[i][j][1]),
                          "+f"(acc[i][j][2]), "+f"(acc[i][j][3])
                        : "r"(af[i][0]), "r"(af[i][1]), "r"(af[i][2]), "r"(af[i][3]),
                          "r"(bf[j][0]), "r"(bf[j][1]));
                }
        }

        cp_wait1();
        __syncthreads();
    }

    #pragma unroll
    for (int i = 0; i < 4; i++) {
        const int r0e = bm + wm + i*16 + u;
        #pragma unroll
        for (int j = 0; j < 4; j++) {
            const int c0 = bn + wn + j*8 + li*2;
            float v0 = acc[i][j][0], v1 = acc[i][j][1];
            float v2 = acc[i][j][2], v3 = acc[i][j][3];
            if (EPI == 1) {
                const float bA = bias[c0], bB = bias[c0+1];
                v0 += bA; v1 += bB; v2 += bA; v3 += bB;
                v0 = (v0 > 20.0f) ? v0 : log1pf(__expf(v0));
                v1 = (v1 > 20.0f) ? v1 : log1pf(__expf(v1));
                v2 = (v2 > 20.0f) ? v2 : log1pf(__expf(v2));
                v3 = (v3 > 20.0f) ? v3 : log1pf(__expf(v3));
            }
            *(float2*)&C[(size_t)r0e * ldc + c0]     = make_float2(v0, v1);
            *(float2*)&C[(size_t)(r0e+8) * ldc + c0] = make_float2(v2, v3);
        }
    }
}

// ---------------- fp32 tiled SGEMM, split-K (B/C part of x_proj: N=32) ----------------
// BM=128, BN=32, BK=16, TM=8, TN=2; k-accumulation order identical to prior version.
template<int BM, int BN, int BK, int TM, int TN>
__global__ __launch_bounds__(256)
void sgemm_splitk_kernel(int M, int N, int KC,
                         const float* __restrict__ A, int lda,
                         const float* __restrict__ Bw, int ldb,
                         float* __restrict__ C, int ldc)
{
    __shared__ float As[BK][BM];
    __shared__ float Bs[BK][BN];

    const int tid = threadIdx.x;
    const int tx  = tid & 15;
    const int ty  = tid >> 4;
    const int bm  = blockIdx.y * BM;
    const int sk  = blockIdx.x;
    const size_t k0base = (size_t)sk * KC;
    C += (size_t)sk * M * ldc;

    float acc[TM][TN];
    #pragma unroll
    for (int i = 0; i < TM; i++)
        #pragma unroll
        for (int j = 0; j < TN; j++) acc[i][j] = 0.0f;

    for (int k0 = 0; k0 < KC; k0 += BK) {
        // A tile: BM*BK/4 float4 loads, strided by 256 threads
        #pragma unroll
        for (int t = tid; t < (BM*BK/4); t += 256) {
            const int a_m = t / (BK/4);
            const int a_k = (t % (BK/4)) * 4;
            float4 v = *(const float4*)&A[(size_t)(bm + a_m)*lda + k0base + k0 + a_k];
            As[a_k+0][a_m] = v.x; As[a_k+1][a_m] = v.y;
            As[a_k+2][a_m] = v.z; As[a_k+3][a_m] = v.w;
        }
        if (tid < (BN*BK/4)) {
            const int b_n = tid / (BK/4);
            const int b_k = (tid % (BK/4)) * 4;
            float4 v = *(const float4*)&Bw[(size_t)b_n*ldb + k0base + k0 + b_k];
            Bs[b_k+0][b_n] = v.x; Bs[b_k+1][b_n] = v.y;
            Bs[b_k+2][b_n] = v.z; Bs[b_k+3][b_n] = v.w;
        }
        __syncthreads();

        #pragma unroll
        for (int k = 0; k < BK; k++) {
            float rm[TM], rn[TN];
            #pragma unroll
            for (int i = 0; i < TM; i++) rm[i] = As[k][ty*TM + i];
            #pragma unroll
            for (int j = 0; j < TN; j++) rn[j] = Bs[k][tx*TN + j];
            #pragma unroll
            for (int i = 0; i < TM; i++)
                #pragma unroll
                for (int j = 0; j < TN; j++)
                    acc[i][j] += rm[i] * rn[j];
        }
        __syncthreads();
    }

    #pragma unroll
    for (int i = 0; i < TM; i++) {
        const int m = bm + ty*TM + i;
        #pragma unroll
        for (int j = 0; j < TN; j++) {
            const int n = tx*TN + j;
            C[(size_t)m*ldc + n] = acc[i][j];
        }
    }
}

// ---------------- depthwise causal conv(k=4) + bias + silu, L-chunked ----------------
#define CLC 64
__global__ __launch_bounds__(256)
void conv_silu_kernel(const float* __restrict__ xz,
                      const float* __restrict__ w,
                      const float* __restrict__ bias,
                      float* __restrict__ xc,
                      float* __restrict__ xcr)
{
    const int d  = blockIdx.x * blockDim.x + threadIdx.x;
    const int b  = blockIdx.z;
    const int l0 = blockIdx.y * CLC;

    const float w0 = w[d*4+0], w1 = w[d*4+1], w2 = w[d*4+2], w3 = w[d*4+3];
    const float bi = bias[d];
    const float* px = xz  + ((size_t)b * L_ + l0) * EI + d;
    float*       po = xc  + ((size_t)b * L_ + l0) * DI + d;
    float*       pr = xcr + ((size_t)b * L_ + l0) * DI + d;

    float x0 = 0.f, x1 = 0.f, x2 = 0.f;
    if (l0 > 0) {
        x0 = px[-(size_t)3 * EI];
        x1 = px[-(size_t)2 * EI];
        x2 = px[-(size_t)1 * EI];
    }
    #pragma unroll 4
    for (int l = 0; l < CLC; l++) {
        float x3 = px[(size_t)l * EI];
        float v  = w0*x0 + w1*x1 + w2*x2 + w3*x3 + bi;
        v = v / (1.0f + __expf(-v));
        po[(size_t)l * DI] = v;
        pr[(size_t)l * DI] = tf32r(v);
        x0 = x1; x1 = x2; x2 = x3;
    }
}

// ---------------- selective scan: state-parallel + cp.async smem staging ----------------
#define SCH 32
__global__ __launch_bounds__(128)
void scan_kernel(const float* __restrict__ xz,
                 const float* __restrict__ xc,
                 const float* __restrict__ dt,
                 const float* __restrict__ bc,
                 const float* __restrict__ A_log,
                 const float* __restrict__ Dp,
                 float* __restrict__ y)
{
    __shared__ float s_dt[2][SCH][32];
    __shared__ float s_xc[2][SCH][32];
    __shared__ float s_z [2][SCH][32];
    __shared__ float s_bc[2][SCH][32];

    const int b    = blockIdx.y;
    const int tid  = threadIdx.x;
    const int wid  = tid >> 5;
    const int lane = tid & 31;
    const int sub  = lane & 3;
    const int cidx = wid * 8 + (lane >> 2);
    const int d0   = blockIdx.x * 32;
    const int d    = d0 + cidx;

    const int lrow = tid >> 3;
    const int lcol = (tid & 7) * 4;

    float negA[4];
    #pragma unroll
    for (int j = 0; j < 4; j++)
        negA[j] = -__expf(A_log[d*DS + sub*4 + j]);
    const float negA0 = -__expf(A_log[d*DS]);

    bool chain = (negA0 != 0.0f);
    #pragma unroll
    for (int n = 1; n < DS; n++) {
        float na = -__expf(A_log[d*DS + n]);
        float r  = na - (float)(n+1) * negA0;
        if (fabsf(r) > 1e-4f * fabsf(na)) chain = false;
    }

    const float Dd = Dp[d];
    float h[4] = {0.f, 0.f, 0.f, 0.f};

    const size_t rb = (size_t)b * L_;
    const float* pdt = dt + rb * DI;
    const float* pxc = xc + rb * DI;
    const float* pz  = xz + rb * EI + DI;
    const float* pbc = bc + rb * 32;
    float*       py  = y  + rb * DI + d;

    #pragma unroll
    for (int c = 0; c < 2; c++) {
        const size_t l0 = (size_t)c * SCH;
        #pragma unroll
        for (int rr = 0; rr < 2; rr++) {
            const int row = lrow + rr*16;
            cp16(&s_dt[c][row][lcol], pdt + (l0 + row) * DI + d0 + lcol);
            cp16(&s_xc[c][row][lcol], pxc + (l0 + row) * DI + d0 + lcol);
            cp16(&s_z [c][row][lcol], pz  + (l0 + row) * EI + d0 + lcol);
            cp16(&s_bc[c][row][lcol], pbc + (l0 + row) * 32 + lcol);
        }
        cp_commit();
    }
    cp_wait1();
    __syncthreads();

    const int NCH = L_ / SCH;
    for (int c = 0; c < NCH; c++) {
        const int buf = c & 1;

        #pragma unroll 4
        for (int i = 0; i < SCH; i++) {
            const float dtv = s_dt[buf][i][cidx];
            const float xv  = s_xc[buf][i][cidx];
            const float zv  = s_z [buf][i][cidx];
            const float bc0 = s_bc[buf][i][lane];

            float dA[4];
            if (chain) {
                const float b1 = __expf(dtv * negA0);
                const float b2 = b1*b1, b3 = b2*b1, b4 = b2*b2;
                const float b8 = b4*b4, b12 = b8*b4;
                const float pw = (sub == 0) ? 1.0f : (sub == 1) ? b4 : (sub == 2) ? b8 : b12;
                dA[0] = pw*b1; dA[1] = pw*b2; dA[2] = pw*b3; dA[3] = pw*b4;
            } else {
                #pragma unroll
                for (int j = 0; j < 4; j++) dA[j] = __expf(dtv * negA[j]);
            }

            const float du = dtv * xv;
            float yp = 0.0f;
            #pragma unroll
            for (int j = 0; j < 4; j++) {
                const float Bn = __shfl_sync(0xFFFFFFFFu, bc0, sub*4 + j);
                const float Cn = __shfl_sync(0xFFFFFFFFu, bc0, 16 + sub*4 + j);
                h[j] = h[j] * dA[j] + du * Bn;
                yp  += h[j] * Cn;
            }
            yp += __shfl_xor_sync(0xFFFFFFFFu, yp, 1);
            yp += __shfl_xor_sync(0xFFFFFFFFu, yp, 2);

            if (sub == 0) {
                const float yv = yp + xv * Dd;
                const float zs = zv / (1.0f + __expf(-zv));
                py[(size_t)(c*SCH + i) * DI] = tf32r(yv * zs);
            }
        }

        __syncthreads();
        if (c + 2 < NCH) {
            const size_t l0 = (size_t)(c + 2) * SCH;
            #pragma unroll
            for (int rr = 0; rr < 2; rr++) {
                const int row = lrow + rr*16;
                cp16(&s_dt[buf][row][lcol], pdt + (l0 + row) * DI + d0 + lcol);
                cp16(&s_xc[buf][row][lcol], pxc + (l0 + row) * DI + d0 + lcol);
                cp16(&s_z [buf][row][lcol], pz  + (l0 + row) * EI + d0 + lcol);
                cp16(&s_bc[buf][row][lcol], pbc + (l0 + row) * 32 + lcol);
            }
        }
        cp_commit();
        cp_wait1();
        __syncthreads();
    }
}

// ---------------- launch ----------------
extern "C" void kernel_launch(void* const* d_in, const int* in_sizes, int n_in,
                              void* d_out, int out_size)
{
    const float* hs    = (const float*)d_in[0];
    const float* w_in  = (const float*)d_in[1];
    const float* convw = (const float*)d_in[2];
    const float* convb = (const float*)d_in[3];
    const float* xpw   = (const float*)d_in[4];
    const float* dtw   = (const float*)d_in[5];
    const float* dtb   = (const float*)d_in[6];
    const float* outw  = (const float*)d_in[7];
    const float* Alog  = (const float*)d_in[8];
    const float* Dp    = (const float*)d_in[9];
    float*       out   = (float*)d_out;

    float *xz, *xc, *xcr, *bc, *bcp, *dtb_, *yb;
    float *hsc, *winc, *dtwc, *outwc, *xpwc, *dtlo, *dtlp;
    cudaGetSymbolAddress((void**)&xz,    g_xz);
    cudaGetSymbolAddress((void**)&xc,    g_xc);
    cudaGetSymbolAddress((void**)&xcr,   g_xcr);
    cudaGetSymbolAddress((void**)&bc,    g_bc);
    cudaGetSymbolAddress((void**)&bcp,   g_bcp);
    cudaGetSymbolAddress((void**)&dtb_,  g_dt);
    cudaGetSymbolAddress((void**)&yb,    g_y);
    cudaGetSymbolAddress((void**)&hsc,   g_hsc);
    cudaGetSymbolAddress((void**)&winc,  g_winc);
    cudaGetSymbolAddress((void**)&dtwc,  g_dtwc);
    cudaGetSymbolAddress((void**)&outwc, g_outwc);
    cudaGetSymbolAddress((void**)&xpwc,  g_xpwc);
    cudaGetSymbolAddress((void**)&dtlo,  g_dtlo);
    cudaGetSymbolAddress((void**)&dtlp,  g_dtlp);

    const dim3 t256(256);
    const size_t msmem = 6 * TSZ32 * sizeof(float);
    const size_t wsmem = 4 * (TSZ_A + TSZ_B) * sizeof(float);

    cudaFuncSetAttribute((const void*)&mma_gemm<1,0>, cudaFuncAttributeMaxDynamicSharedMemorySize, (int)msmem);
    cudaFuncSetAttribute((const void*)&mma_gemm<0,1>, cudaFuncAttributeMaxDynamicSharedMemorySize, (int)msmem);
    cudaFuncSetAttribute((const void*)&mma_gemm_wide, cudaFuncAttributeMaxDynamicSharedMemorySize, (int)wsmem);

    // 0) fused tf32 pre-rounding
    {
        const size_t n0 = (size_t)ML*DM/4, n1 = (size_t)EI*DM/4,
                     n2 = (size_t)DI*DTR/4, n3 = (size_t)DM*DI/4,
                     n4 = (size_t)DTR*DI/4;
        const size_t nt = n0 + n1 + n2 + n3 + n4;
        round_all_kernel<<<(unsigned)((nt+255)/256), t256>>>(
            hs, hsc, n0, w_in, winc, n1, dtw, dtwc, n2, outw, outwc, n3, xpw, xpwc, n4);
    }

    // 1) in_proj (wide tf32 mma)
    mma_gemm_wide<<<dim3(EI/256, ML/128), dim3(512), wsmem>>>(
        ML, EI, DM, hsc, DM, winc, DM, xz, EI);

    // 2) depthwise conv + silu
    conv_silu_kernel<<<dim3(DI/256, L_/CLC, B_), t256>>>(xz, convw, convb, xc, xcr);

    // 3a) x_proj B/C (fp32 split-K x8, BM=128 TM=8)
    sgemm_splitk_kernel<128,32,16,8,2><<<dim3(KS_BC, ML/128), t256>>>(
        ML, 32, DI/KS_BC, xc, DI, xpw + (size_t)DTR*DI, DI, bcp, 32);

    // 3b) x_proj dt_lo (tf32 mma split-K x8)
    mma_gemm<0,1><<<dim3(KS_DT, ML/128), t256, msmem>>>(
        ML, DTR, DI/KS_DT, xcr, DI, xpwc, DI, dtlp, DTR, nullptr);

    // 3c) reduce split-K partials
    {
        const size_t nt = (size_t)ML*32/4 + (size_t)ML*DTR/4;
        reduce_splitk_kernel<<<(unsigned)((nt+255)/256), t256>>>(bcp, bc, dtlp, dtlo);
    }

    // 4) dt_proj + softplus (tf32 mma)
    mma_gemm<1,0><<<dim3(DI/128, ML/128), t256, msmem>>>(
        ML, DI, DTR, dtlo, DTR, dtwc, DTR, dtb_, DI, dtb);

    // 5) selective scan (state-parallel, cp.async staged, SCH=32)
    scan_kernel<<<dim3(DI/32, B_), dim3(128)>>>(
        xz, xc, dtb_, bc, Alog, Dp, yb);

    // 6) out_proj (wide tf32 mma)
    mma_gemm_wide<<<dim3(DM/256, ML/128), dim3(512), wsmem>>>(
        ML, DM, DI, yb, DI, outwc, DI, out, DM);
}

// round 17
// speedup vs baseline: 1.3373x; 1.0024x over previous
#include <cuda_runtime.h>
#include <cstdint>
#include <cstddef>

// ---------------- problem constants ----------------
#define B_   2
#define L_   2048
#define DM   2048          // d_model
#define DI   4096          // d_inner
#define EI   8192          // 2*d_inner
#define DS   16            // d_state
#define DTR  128           // dt_rank
#define XD   160           // dt_rank + 2*d_state
#define ML   (B_*L_)       // 4096 rows

#define KS_BC 8            // split-K for B/C sgemm
#define KS_DT 8            // split-K for dt_lo mma

// ---------------- scratch (device globals; no allocation allowed) ----------------
__device__ float g_xz  [(size_t)ML * EI];
__device__ float g_xc  [(size_t)ML * DI];   // conv+silu (exact fp32)
__device__ float g_bc  [(size_t)ML * 32];   // B(16) + C(16) per row, fp32
__device__ float g_bcp [(size_t)KS_BC * ML * 32];   // split-K partials
__device__ float g_dt  [(size_t)ML * DI];
__device__ float g_y   [(size_t)ML * DI];   // scan output (tf32-rounded)
__device__ float g_hsc [(size_t)ML * DM];   // tf32-rounded hidden_states
__device__ float g_winc[(size_t)EI * DM];   // tf32-rounded in_proj_weight
__device__ float g_dtwc[(size_t)DI * DTR];  // tf32-rounded dt_proj_weight
__device__ float g_outwc[(size_t)DM * DI];  // tf32-rounded out_proj_weight
__device__ float g_dtlo[(size_t)ML * DTR];  // tf32 dt_lo (compact)
__device__ float g_dtlp[(size_t)KS_DT * ML * DTR];  // split-K partials

__device__ __forceinline__ unsigned f2tf32(float f) {
    unsigned u;
    asm("cvt.rna.tf32.f32 %0, %1;" : "=r"(u) : "f"(f));
    return u;
}
__device__ __forceinline__ float tf32r(float f) {
    return __uint_as_float(f2tf32(f));
}
__device__ __forceinline__ unsigned cvt_bits(unsigned raw) {
    return f2tf32(__uint_as_float(raw));
}

// ---------------- fused tf32 rounding: 4 segments in one launch ----------------
__global__ __launch_bounds__(256)
void round_all_kernel(const float* s0, float* d0, size_t n0,
                      const float* s1, float* d1, size_t n1,
                      const float* s2, float* d2, size_t n2,
                      const float* s3, float* d3, size_t n3)
{
    size_t i = (size_t)blockIdx.x * blockDim.x + threadIdx.x;
    const float* s; float* d;
    if (i < n0) { s = s0; d = d0; }
    else if ((i -= n0) < n1) { s = s1; d = d1; }
    else if ((i -= n1) < n2) { s = s2; d = d2; }
    else if ((i -= n2) < n3) { s = s3; d = d3; }
    else return;
    float4 v = ((const float4*)s)[i];
    v.x = tf32r(v.x); v.y = tf32r(v.y); v.z = tf32r(v.z); v.w = tf32r(v.w);
    ((float4*)d)[i] = v;
}

// ---------------- split-K reduce: bc (8 partials) + dtlo (8 partials, tf32r) ----------------
__global__ __launch_bounds__(256)
void reduce_splitk_kernel(const float* __restrict__ bcp, float* __restrict__ bc,
                          const float* __restrict__ dtlp, float* __restrict__ dtlo)
{
    const size_t nBC = (size_t)ML * 32 / 4;
    const size_t nDT = (size_t)ML * DTR / 4;
    size_t i = (size_t)blockIdx.x * blockDim.x + threadIdx.x;
    if (i < nBC) {
        float4 a = ((const float4*)bcp)[i];
        #pragma unroll
        for (int s = 1; s < KS_BC; s++) {
            float4 p = ((const float4*)(bcp + (size_t)s * ML * 32))[i];
            a.x += p.x; a.y += p.y; a.z += p.z; a.w += p.w;
        }
        ((float4*)bc)[i] = a;
    } else if ((i -= nBC) < nDT) {
        float4 a = ((const float4*)dtlp)[i];
        #pragma unroll
        for (int s = 1; s < KS_DT; s++) {
            float4 p = ((const float4*)(dtlp + (size_t)s * ML * DTR))[i];
            a.x += p.x; a.y += p.y; a.z += p.z; a.w += p.w;
        }
        a.x = tf32r(a.x); a.y = tf32r(a.y); a.z = tf32r(a.z); a.w = tf32r(a.w);
        ((float4*)dtlo)[i] = a;
    }
}

// ---------------- async-copy + ldmatrix helpers ----------------
__device__ __forceinline__ void cp16(float* smem_dst, const float* gmem_src) {
    unsigned s = (unsigned)__cvta_generic_to_shared(smem_dst);
    asm volatile("cp.async.cg.shared.global [%0], [%1], 16;\n" :: "r"(s), "l"(gmem_src));
}
__device__ __forceinline__ void cp_commit() {
    asm volatile("cp.async.commit_group;\n");
}
__device__ __forceinline__ void cp_wait1() {
    asm volatile("cp.async.wait_group 1;\n");
}
__device__ __forceinline__ void cp_wait2() {
    asm volatile("cp.async.wait_group 2;\n");
}
__device__ __forceinline__ void ldsm4(unsigned& r0, unsigned& r1, unsigned& r2, unsigned& r3,
                                      unsigned addr) {
    asm volatile("ldmatrix.sync.aligned.m8n8.x4.shared.b16 {%0,%1,%2,%3}, [%4];"
                 : "=r"(r0), "=r"(r1), "=r"(r2), "=r"(r3) : "r"(addr));
}

// =========================================================================
// WIDE TF32 GEMM: BM=128, BN=256, BK=32, 512 threads (16 warps, 2m x 8n),
// warp tile 64x32, 4-stage cp.async (wait_group 2), ldmatrix fragments.
// =========================================================================
#define TSZ_A 4096
#define TSZ_B 8192
#define STB_A 16384u
#define STB_B 32768u

__global__ __launch_bounds__(512, 1)
void mma_gemm_wide(int M, int N, int K,
                   const float* __restrict__ A, int lda,
                   const float* __restrict__ Bw, int ldb,
                   float* __restrict__ C, int ldc)
{
    extern __shared__ float smem[];
    float* As = smem;
    float* Bs = smem + 4*TSZ_A;

    const int tid  = threadIdx.x;
    const int lane = tid & 31;
    const int warp = tid >> 5;
    const int wm   = (warp & 1) * 64;
    const int wn   = (warp >> 1) * 32;
    const int bm   = blockIdx.y * 128;
    const int bn   = blockIdx.x * 256;

    const int q     = tid & 7;
    const int r0    = tid >> 3;
    const int pq    = q ^ (r0 & 7);
    const int dBase = r0*32 + pq*4;

    const float* gA = A  + (size_t)(bm + r0) * lda + q*4;
    const float* gB = Bw + (size_t)(bn + r0) * ldb + q*4;

    const int g    = lane >> 3;
    const int kg   = g >> 1;
    const int sub8 = (g & 1) << 3;
    const int lr   = lane & 7;
    const unsigned aSh = (unsigned)__cvta_generic_to_shared(As);
    const unsigned bSh = (unsigned)__cvta_generic_to_shared(Bs);
    const unsigned aBase  = aSh + (unsigned)(wm + sub8 + lr) * 128;
    const unsigned bBase0 = bSh + (unsigned)(wn + sub8 + lr) * 128;
    const unsigned bBase1 = bBase0 + 16*128;
    unsigned tks[4];
    #pragma unroll
    for (int ks = 0; ks < 4; ks++)
        tks[ks] = (unsigned)(((((ks << 1) + kg) ^ lr) & 7) << 4);

    const int u  = lane >> 2;
    const int li = lane & 3;

    float acc[4][4][4];
    #pragma unroll
    for (int i = 0; i < 4; i++)
        #pragma unroll
        for (int j = 0; j < 4; j++)
            #pragma unroll
            for (int r = 0; r < 4; r++) acc[i][j][r] = 0.0f;

    const int KT = K / 32;

    #pragma unroll
    for (int s = 0; s < 2; s++) {
        const size_t ko = (size_t)s * 32;
        #pragma unroll
        for (int i = 0; i < 2; i++)
            cp16(As + s*TSZ_A + dBase + i*2048, gA + (size_t)i*64*lda + ko);
        #pragma unroll
        for (int i = 0; i < 4; i++)
            cp16(Bs + s*TSZ_B + dBase + i*2048, gB + (size_t)i*64*ldb + ko);
        cp_commit();
    }

    for (int kt = 0; kt < KT; kt++) {
        const int cur = kt & 3;
        if (kt + 2 < KT) {
            const int st = (kt + 2) & 3;
            const size_t ko = (size_t)(kt + 2) * 32;
            #pragma unroll
            for (int i = 0; i < 2; i++)
                cp16(As + st*TSZ_A + dBase + i*2048, gA + (size_t)i*64*lda + ko);
            #pragma unroll
            for (int i = 0; i < 4; i++)
                cp16(Bs + st*TSZ_B + dBase + i*2048, gB + (size_t)i*64*ldb + ko);
        }
        cp_commit();
        cp_wait2();
        __syncthreads();

        const unsigned aOff  = aBase  + (unsigned)cur * STB_A;
        const unsigned bOff0 = bBase0 + (unsigned)cur * STB_B;
        const unsigned bOff1 = bBase1 + (unsigned)cur * STB_B;

        #pragma unroll
        for (int ks = 0; ks < 4; ks++) {
            unsigned af[4][4];
            unsigned bf[4][2];
            #pragma unroll
            for (int i = 0; i < 4; i++)
                ldsm4(af[i][0], af[i][1], af[i][2], af[i][3],
                      aOff + (unsigned)i*2048 + tks[ks]);
            ldsm4(bf[0][0], bf[1][0], bf[0][1], bf[1][1], bOff0 + tks[ks]);
            ldsm4(bf[2][0], bf[3][0], bf[2][1], bf[3][1], bOff1 + tks[ks]);

            #pragma unroll
            for (int i = 0; i < 4; i++)
                #pragma unroll
                for (int j = 0; j < 4; j++) {
                    asm volatile(
                        "mma.sync.aligned.m16n8k8.row.col.f32.tf32.tf32.f32 "
                        "{%0,%1,%2,%3}, {%4,%5,%6,%7}, {%8,%9}, {%0,%1,%2,%3};"
                        : "+f"(acc[i][j][0]), "+f"(acc[i][j][1]),
                          "+f"(acc[i][j][2]), "+f"(acc[i][j][3])
                        : "r"(af[i][0]), "r"(af[i][1]), "r"(af[i][2]), "r"(af[i][3]),
                          "r"(bf[j][0]), "r"(bf[j][1]));
                }
        }
    }

    #pragma unroll
    for (int i = 0; i < 4; i++) {
        const int r0e = bm + wm + i*16 + u;
        #pragma unroll
        for (int j = 0; j < 4; j++) {
            const int c0 = bn + wn + j*8 + li*2;
            *(float2*)&C[(size_t)r0e * ldc + c0]     = make_float2(acc[i][j][0], acc[i][j][1]);
            *(float2*)&C[(size_t)(r0e+8) * ldc + c0] = make_float2(acc[i][j][2], acc[i][j][3]);
        }
    }
}

// ================= mma.sync TF32 GEMM BN=128 =================
// EPI: 0 = none, 1 = softplus(v+bias[n])
// SPLITK: blockIdx.x = k-split index (N must be 128); partial -> C + split*M*ldc
// CVT: 1 = raw fp32 inputs, cvt.rna.tf32 per fragment (use only in latency-bound launches)
#define TSZ32 4096
#define STB   16384u

template<int EPI, int SPLITK, int CVT>
__global__ __launch_bounds__(256, 2)
void mma_gemm(int M, int N, int K,
              const float* __restrict__ A, int lda,
              const float* __restrict__ Bw, int ldb,
              float* __restrict__ C, int ldc,
              const float* __restrict__ bias)
{
    extern __shared__ float smem[];
    float* As = smem;
    float* Bs = smem + 3*TSZ32;

    const int tid  = threadIdx.x;
    const int lane = tid & 31;
    const int warp = tid >> 5;
    const int wm   = (warp & 1) * 64;
    const int wn   = (warp >> 1) * 32;
    const int bm   = blockIdx.y * 128;
    int bn = 0;
    if (SPLITK) {
        const int sk = blockIdx.x;
        A  += (size_t)sk * K;
        Bw += (size_t)sk * K;
        C  += (size_t)sk * M * ldc;
    } else {
        bn = blockIdx.x * 128;
    }

    const int q     = tid & 7;
    const int r0    = tid >> 3;
    const int pq    = q ^ (r0 & 7);
    const int dBase = r0*32 + pq*4;

    const float* gA = A  + (size_t)(bm + r0) * lda + q*4;
    const float* gB = Bw + (size_t)(bn + r0) * ldb + q*4;

    const int g    = lane >> 3;
    const int kg   = g >> 1;
    const int sub8 = (g & 1) << 3;
    const int lr   = lane & 7;
    const unsigned aSh = (unsigned)__cvta_generic_to_shared(As);
    const unsigned bSh = (unsigned)__cvta_generic_to_shared(Bs);
    const unsigned aBase  = aSh + (unsigned)(wm + sub8 + lr) * 128;
    const unsigned bBase0 = bSh + (unsigned)(wn + sub8 + lr) * 128;
    const unsigned bBase1 = bBase0 + 16*128;
    unsigned tks[4];
    #pragma unroll
    for (int ks = 0; ks < 4; ks++)
        tks[ks] = (unsigned)(((((ks << 1) + kg) ^ lr) & 7) << 4);

    const int u  = lane >> 2;
    const int li = lane & 3;

    float acc[4][4][4];
    #pragma unroll
    for (int i = 0; i < 4; i++)
        #pragma unroll
        for (int j = 0; j < 4; j++)
            #pragma unroll
            for (int r = 0; r < 4; r++) acc[i][j][r] = 0.0f;

    const int KT = K / 32;

    #pragma unroll
    for (int s = 0; s < 2; s++) {
        const size_t ko = (size_t)s * 32;
        #pragma unroll
        for (int i = 0; i < 4; i++) {
            cp16(As + s*TSZ32 + dBase + i*1024, gA + (size_t)i*32*lda + ko);
            cp16(Bs + s*TSZ32 + dBase + i*1024, gB + (size_t)i*32*ldb + ko);
        }
        cp_commit();
    }
    cp_wait1();
    __syncthreads();

    for (int kt = 0; kt < KT; kt++) {
        const int cur = kt % 3;
        if (kt + 2 < KT) {
            const int st = (kt + 2) % 3;
            const size_t ko = (size_t)(kt + 2) * 32;
            #pragma unroll
            for (int i = 0; i < 4; i++) {
                cp16(As + st*TSZ32 + dBase + i*1024, gA + (size_t)i*32*lda + ko);
                cp16(Bs + st*TSZ32 + dBase + i*1024, gB + (size_t)i*32*ldb + ko);
            }
        }
        cp_commit();

        const unsigned aOff  = aBase  + (unsigned)cur * STB;
        const unsigned bOff0 = bBase0 + (unsigned)cur * STB;
        const unsigned bOff1 = bBase1 + (unsigned)cur * STB;

        #pragma unroll
        for (int ks = 0; ks < 4; ks++) {
            unsigned af[4][4];
            unsigned bf[4][2];
            #pragma unroll
            for (int i = 0; i < 4; i++)
                ldsm4(af[i][0], af[i][1], af[i][2], af[i][3],
                      aOff + (unsigned)i*2048 + tks[ks]);
            ldsm4(bf[0][0], bf[1][0], bf[0][1], bf[1][1], bOff0 + tks[ks]);
            ldsm4(bf[2][0], bf[3][0], bf[2][1], bf[3][1], bOff1 + tks[ks]);

            if (CVT) {
                #pragma unroll
                for (int i = 0; i < 4; i++)
                    #pragma unroll
                    for (int r = 0; r < 4; r++) af[i][r] = cvt_bits(af[i][r]);
                #pragma unroll
                for (int j = 0; j < 4; j++) {
                    bf[j][0] = cvt_bits(bf[j][0]);
                    bf[j][1] = cvt_bits(bf[j][1]);
                }
            }

            #pragma unroll
            for (int i = 0; i < 4; i++)
                #pragma unroll
                for (int j = 0; j < 4; j++) {
                    asm volatile(
                        "mma.sync.aligned.m16n8k8.row.col.f32.tf32.tf32.f32 "
                        "{%0,%1,%2,%3}, {%4,%5,%6,%7}, {%8,%9}, {%0,%1,%2,%3};"
                        : "+f"(acc[i][j][0]), "+f"(acc[i][j][1]),
                          "+f"(acc[i][j][2]), "+f"(acc[i][j][3])
                        : "r"(af[i][0]), "r"(af[i][1]), "r"(af[i][2]), "r"(af[i][3]),
                          "r"(bf[j][0]), "r"(bf[j][1]));
                }
        }

        cp_wait1();
        __syncthreads();
    }

    #pragma unroll
    for (int i = 0; i < 4; i++) {
        const int r0e = bm + wm + i*16 + u;
        #pragma unroll
        for (int j = 0; j < 4; j++) {
            const int c0 = bn + wn + j*8 + li*2;
            float v0 = acc[i][j][0], v1 = acc[i][j][1];
            float v2 = acc[i][j][2], v3 = acc[i][j][3];
            if (EPI == 1) {
                const float bA = bias[c0], bB = bias[c0+1];
                v0 += bA; v1 += bB; v2 += bA; v3 += bB;
                v0 = (v0 > 20.0f) ? v0 : log1pf(__expf(v0));
                v1 = (v1 > 20.0f) ? v1 : log1pf(__expf(v1));
                v2 = (v2 > 20.0f) ? v2 : log1pf(__expf(v2));
                v3 = (v3 > 20.0f) ? v3 : log1pf(__expf(v3));
            }
            *(float2*)&C[(size_t)r0e * ldc + c0]     = make_float2(v0, v1);
            *(float2*)&C[(size_t)(r0e+8) * ldc + c0] = make_float2(v2, v3);
        }
    }
}

// ---------------- fp32 tiled SGEMM, split-K (B/C part of x_proj: N=32) ----------------
template<int BM, int BN, int BK, int TM, int TN>
__global__ __launch_bounds__(256)
void sgemm_splitk_kernel(int M, int N, int KC,
                         const float* __restrict__ A, int lda,
                         const float* __restrict__ Bw, int ldb,
                         float* __restrict__ C, int ldc)
{
    __shared__ float As[BK][BM];
    __shared__ float Bs[BK][BN];

    const int tid = threadIdx.x;
    const int tx  = tid & 15;
    const int ty  = tid >> 4;
    const int bm  = blockIdx.y * BM;
    const int sk  = blockIdx.x;
    const size_t k0base = (size_t)sk * KC;
    C += (size_t)sk * M * ldc;

    float acc[TM][TN];
    #pragma unroll
    for (int i = 0; i < TM; i++)
        #pragma unroll
        for (int j = 0; j < TN; j++) acc[i][j] = 0.0f;

    for (int k0 = 0; k0 < KC; k0 += BK) {
        #pragma unroll
        for (int t = tid; t < (BM*BK/4); t += 256) {
            const int a_m = t / (BK/4);
            const int a_k = (t % (BK/4)) * 4;
            float4 v = *(const float4*)&A[(size_t)(bm + a_m)*lda + k0base + k0 + a_k];
            As[a_k+0][a_m] = v.x; As[a_k+1][a_m] = v.y;
            As[a_k+2][a_m] = v.z; As[a_k+3][a_m] = v.w;
        }
        if (tid < (BN*BK/4)) {
            const int b_n = tid / (BK/4);
            const int b_k = (tid % (BK/4)) * 4;
            float4 v = *(const float4*)&Bw[(size_t)b_n*ldb + k0base + k0 + b_k];
            Bs[b_k+0][b_n] = v.x; Bs[b_k+1][b_n] = v.y;
            Bs[b_k+2][b_n] = v.z; Bs[b_k+3][b_n] = v.w;
        }
        __syncthreads();

        #pragma unroll
        for (int k = 0; k < BK; k++) {
            float rm[TM], rn[TN];
            #pragma unroll
            for (int i = 0; i < TM; i++) rm[i] = As[k][ty*TM + i];
            #pragma unroll
            for (int j = 0; j < TN; j++) rn[j] = Bs[k][tx*TN + j];
            #pragma unroll
            for (int i = 0; i < TM; i++)
                #pragma unroll
                for (int j = 0; j < TN; j++)
                    acc[i][j] += rm[i] * rn[j];
        }
        __syncthreads();
    }

    #pragma unroll
    for (int i = 0; i < TM; i++) {
        const int m = bm + ty*TM + i;
        #pragma unroll
        for (int j = 0; j < TN; j++) {
            const int n = tx*TN + j;
            C[(size_t)m*ldc + n] = acc[i][j];
        }
    }
}

// ---------------- depthwise causal conv(k=4) + bias + silu, L-chunked ----------------
#define CLC 64
__global__ __launch_bounds__(256)
void conv_silu_kernel(const float* __restrict__ xz,
                      const float* __restrict__ w,
                      const float* __restrict__ bias,
                      float* __restrict__ xc)
{
    const int d  = blockIdx.x * blockDim.x + threadIdx.x;
    const int b  = blockIdx.z;
    const int l0 = blockIdx.y * CLC;

    const float w0 = w[d*4+0], w1 = w[d*4+1], w2 = w[d*4+2], w3 = w[d*4+3];
    const float bi = bias[d];
    const float* px = xz + ((size_t)b * L_ + l0) * EI + d;
    float*       po = xc + ((size_t)b * L_ + l0) * DI + d;

    float x0 = 0.f, x1 = 0.f, x2 = 0.f;
    if (l0 > 0) {
        x0 = px[-(size_t)3 * EI];
        x1 = px[-(size_t)2 * EI];
        x2 = px[-(size_t)1 * EI];
    }
    #pragma unroll 4
    for (int l = 0; l < CLC; l++) {
        float x3 = px[(size_t)l * EI];
        float v  = w0*x0 + w1*x1 + w2*x2 + w3*x3 + bi;
        v = v / (1.0f + __expf(-v));
        po[(size_t)l * DI] = v;
        x0 = x1; x1 = x2; x2 = x3;
    }
}

// ---------------- selective scan: 16 channels/block, 64 threads, cp.async staged ----------------
#define SCH 32
__global__ __launch_bounds__(64)
void scan_kernel(const float* __restrict__ xz,
                 const float* __restrict__ xc,
                 const float* __restrict__ dt,
                 const float* __restrict__ bc,
                 const float* __restrict__ A_log,
                 const float* __restrict__ Dp,
                 float* __restrict__ y)
{
    __shared__ float s_dt[2][SCH][16];
    __shared__ float s_xc[2][SCH][16];
    __shared__ float s_z [2][SCH][16];
    __shared__ float s_bc[2][SCH][32];

    const int b    = blockIdx.y;
    const int tid  = threadIdx.x;         // 0..63
    const int wid  = tid >> 5;            // 0..1
    const int lane = tid & 31;
    const int sub  = lane & 3;            // state group 0..3
    const int cidx = wid * 8 + (lane >> 2);   // channel within block 0..15
    const int d0   = blockIdx.x * 16;
    const int d    = d0 + cidx;

    // loaders: dt/xc/z rows of 16 floats = 4 cp16; 32 rows -> 128 cp16 -> 2/thread
    const int lrow = tid >> 2;            // 0..15 (+16)
    const int lcol = (tid & 3) * 4;       // 0,4,8,12
    // bc rows of 32 floats = 8 cp16; 32 rows -> 256 cp16 -> 4/thread
    const int brow = tid >> 3;            // 0..7 (+8,+16,+24)
    const int bcol = (tid & 7) * 4;       // 0..28

    float negA[4];
    #pragma unroll
    for (int j = 0; j < 4; j++)
        negA[j] = -__expf(A_log[d*DS + sub*4 + j]);
    const float negA0 = -__expf(A_log[d*DS]);

    bool chain = (negA0 != 0.0f);
    #pragma unroll
    for (int n = 1; n < DS; n++) {
        float na = -__expf(A_log[d*DS + n]);
        float r  = na - (float)(n+1) * negA0;
        if (fabsf(r) > 1e-4f * fabsf(na)) chain = false;
    }

    const float Dd = Dp[d];
    float h[4] = {0.f, 0.f, 0.f, 0.f};

    const size_t rb = (size_t)b * L_;
    const float* pdt = dt + rb * DI;
    const float* pxc = xc + rb * DI;
    const float* pz  = xz + rb * EI + DI;
    const float* pbc = bc + rb * 32;
    float*       py  = y  + rb * DI + d;

    // issue chunks 0 and 1
    #pragma unroll
    for (int c = 0; c < 2; c++) {
        const size_t l0 = (size_t)c * SCH;
        #pragma unroll
        for (int rr = 0; rr < 2; rr++) {
            const int row = lrow + rr*16;
            cp16(&s_dt[c][row][lcol], pdt + (l0 + row) * DI + d0 + lcol);
            cp16(&s_xc[c][row][lcol], pxc + (l0 + row) * DI + d0 + lcol);
            cp16(&s_z [c][row][lcol], pz  + (l0 + row) * EI + d0 + lcol);
        }
        #pragma unroll
        for (int rr = 0; rr < 4; rr++) {
            const int row = brow + rr*8;
            cp16(&s_bc[c][row][bcol], pbc + (l0 + row) * 32 + bcol);
        }
        cp_commit();
    }
    cp_wait1();
    __syncthreads();

    const int NCH = L_ / SCH;
    for (int c = 0; c < NCH; c++) {
        const int buf = c & 1;

        #pragma unroll 4
        for (int i = 0; i < SCH; i++) {
            const float dtv = s_dt[buf][i][cidx];
            const float xv  = s_xc[buf][i][cidx];
            const float zv  = s_z [buf][i][cidx];
            const float bc0 = s_bc[buf][i][lane];

            float dA[4];
            if (chain) {
                const float b1 = __expf(dtv * negA0);
                const float b2 = b1*b1, b3 = b2*b1, b4 = b2*b2;
                const float b8 = b4*b4, b12 = b8*b4;
                const float pw = (sub == 0) ? 1.0f : (sub == 1) ? b4 : (sub == 2) ? b8 : b12;
                dA[0] = pw*b1; dA[1] = pw*b2; dA[2] = pw*b3; dA[3] = pw*b4;
            } else {
                #pragma unroll
                for (int j = 0; j < 4; j++) dA[j] = __expf(dtv * negA[j]);
            }

            const float du = dtv * xv;
            float yp = 0.0f;
            #pragma unroll
            for (int j = 0; j < 4; j++) {
                const float Bn = __shfl_sync(0xFFFFFFFFu, bc0, sub*4 + j);
                const float Cn = __shfl_sync(0xFFFFFFFFu, bc0, 16 + sub*4 + j);
                h[j] = h[j] * dA[j] + du * Bn;
                yp  += h[j] * Cn;
            }
            yp += __shfl_xor_sync(0xFFFFFFFFu, yp, 1);
            yp += __shfl_xor_sync(0xFFFFFFFFu, yp, 2);

            if (sub == 0) {
                const float yv = yp + xv * Dd;
                const float zs = zv / (1.0f + __expf(-zv));
                py[(size_t)(c*SCH + i) * DI] = tf32r(yv * zs);
            }
        }

        __syncthreads();
        if (c + 2 < NCH) {
            const size_t l0 = (size_t)(c + 2) * SCH;
            #pragma unroll
            for (int rr = 0; rr < 2; rr++) {
                const int row = lrow + rr*16;
                cp16(&s_dt[buf][row][lcol], pdt + (l0 + row) * DI + d0 + lcol);
                cp16(&s_xc[buf][row][lcol], pxc + (l0 + row) * DI + d0 + lcol);
                cp16(&s_z [buf][row][lcol], pz  + (l0 + row) * EI + d0 + lcol);
            }
            #pragma unroll
            for (int rr = 0; rr < 4; rr++) {
                const int row = brow + rr*8;
                cp16(&s_bc[buf][row][bcol], pbc + (l0 + row) * 32 + bcol);
            }
        }
        cp_commit();
        cp_wait1();
        __syncthreads();
    }
}

// ---------------- launch ----------------
extern "C" void kernel_launch(void* const* d_in, const int* in_sizes, int n_in,
                              void* d_out, int out_size)
{
    const float* hs    = (const float*)d_in[0];
    const float* w_in  = (const float*)d_in[1];
    const float* convw = (const float*)d_in[2];
    const float* convb = (const float*)d_in[3];
    const float* xpw   = (const float*)d_in[4];
    const float* dtw   = (const float*)d_in[5];
    const float* dtb   = (const float*)d_in[6];
    const float* outw  = (const float*)d_in[7];
    const float* Alog  = (const float*)d_in[8];
    const float* Dp    = (const float*)d_in[9];
    float*       out   = (float*)d_out;

    float *xz, *xc, *bc, *bcp, *dtb_, *yb;
    float *hsc, *winc, *dtwc, *outwc, *dtlo, *dtlp;
    cudaGetSymbolAddress((void**)&xz,    g_xz);
    cudaGetSymbolAddress((void**)&xc,    g_xc);
    cudaGetSymbolAddress((void**)&bc,    g_bc);
    cudaGetSymbolAddress((void**)&bcp,   g_bcp);
    cudaGetSymbolAddress((void**)&dtb_,  g_dt);
    cudaGetSymbolAddress((void**)&yb,    g_y);
    cudaGetSymbolAddress((void**)&hsc,   g_hsc);
    cudaGetSymbolAddress((void**)&winc,  g_winc);
    cudaGetSymbolAddress((void**)&dtwc,  g_dtwc);
    cudaGetSymbolAddress((void**)&outwc, g_outwc);
    cudaGetSymbolAddress((void**)&dtlo,  g_dtlo);
    cudaGetSymbolAddress((void**)&dtlp,  g_dtlp);

    const dim3 t256(256);
    const size_t msmem = 6 * TSZ32 * sizeof(float);
    const size_t wsmem = 4 * (TSZ_A + TSZ_B) * sizeof(float);

    cudaFuncSetAttribute((const void*)&mma_gemm<1,0,0>, cudaFuncAttributeMaxDynamicSharedMemorySize, (int)msmem);
    cudaFuncSetAttribute((const void*)&mma_gemm<0,1,1>, cudaFuncAttributeMaxDynamicSharedMemorySize, (int)msmem);
    cudaFuncSetAttribute((const void*)&mma_gemm_wide,   cudaFuncAttributeMaxDynamicSharedMemorySize, (int)wsmem);

    // 0) fused tf32 pre-rounding: hs, w_in, dtw, outw (xpw handled by CVT path)
    {
        const size_t n0 = (size_t)ML*DM/4, n1 = (size_t)EI*DM/4,
                     n2 = (size_t)DI*DTR/4, n3 = (size_t)DM*DI/4;
        const size_t nt = n0 + n1 + n2 + n3;
        round_all_kernel<<<(unsigned)((nt+255)/256), t256>>>(
            hs, hsc, n0, w_in, winc, n1, dtw, dtwc, n2, outw, outwc, n3);
    }

    // 1) in_proj (wide tf32 mma)
    mma_gemm_wide<<<dim3(EI/256, ML/128), dim3(512), wsmem>>>(
        ML, EI, DM, hsc, DM, winc, DM, xz, EI);

    // 2) depthwise conv + silu (exact xc only)
    conv_silu_kernel<<<dim3(DI/256, L_/CLC, B_), t256>>>(xz, convw, convb, xc);

    // 3a) x_proj B/C (fp32 split-K x8, BM=128 TM=8)
    sgemm_splitk_kernel<128,32,16,8,2><<<dim3(KS_BC, ML/128), t256>>>(
        ML, 32, DI/KS_BC, xc, DI, xpw + (size_t)DTR*DI, DI, bcp, 32);

    // 3b) x_proj dt_lo (tf32 mma split-K x8, raw inputs + in-fragment cvt)
    mma_gemm<0,1,1><<<dim3(KS_DT, ML/128), t256, msmem>>>(
        ML, DTR, DI/KS_DT, xc, DI, xpw, DI, dtlp, DTR, nullptr);

    // 3c) reduce split-K partials (bc exact, dtlo tf32-rounded)
    {
        const size_t nt = (size_t)ML*32/4 + (size_t)ML*DTR/4;
        reduce_splitk_kernel<<<(unsigned)((nt+255)/256), t256>>>(bcp, bc, dtlp, dtlo);
    }

    // 4) dt_proj + softplus (tf32 mma, pre-rounded inputs)
    mma_gemm<1,0,0><<<dim3(DI/128, ML/128), t256, msmem>>>(
        ML, DI, DTR, dtlo, DTR, dtwc, DTR, dtb_, DI, dtb);

    // 5) selective scan (16 channels/block, 512 CTAs)
    scan_kernel<<<dim3(DI/16, B_), dim3(64)>>>(
        xz, xc, dtb_, bc, Alog, Dp, yb);

    // 6) out_proj (wide tf32 mma)
    mma_gemm_wide<<<dim3(DM/256, ML/128), dim3(512), wsmem>>>(
        ML, DM, DI, yb, DI, outwc, DI, out, DM);
}